// round 11
// baseline (speedup 1.0000x reference)
#include <cuda_runtime.h>
#include <cuda_bf16.h>
#include <mma.h>
#include <math.h>

using namespace nvcuda;

// ---------------- problem constants ----------------
#define NTOK 8192
#define HDIM 1024
#define IDIM 2048
#define NEXP 8
#define NSLOT (NTOK*2)

#define BM 128
#define BN 128
#define BK 64             // int8 k-chunk (64 bytes per row)
#define MAXT 136

#define APITCH 80         // int8 row pitch (bytes); 80 mod 128 -> conflict-free 16B units
#define SPITCH 132        // float stage pitch (epilogue)

// smem layout (bytes)
#define SM_ROWTOK 0        // 128 ints
#define SM_ROWSC  512      // 128 floats
#define SM_COLSC  1024     // 128 floats
#define SM_STG0   2048
#define TILE_B    (128*APITCH)         // 10240 per operand tile
#define STG_SZ    (4*TILE_B)           // 40960 per stage (Ah,Al,Bh,Bl int8)
#define OFF_AH 0
#define OFF_AL (1*TILE_B)
#define OFF_BH (2*TILE_B)
#define OFF_BL (3*TILE_B)
#define NSTAGE 3
#define DSMEM (SM_STG0 + NSTAGE*STG_SZ)   // 124928; epilogue float stage (69632) fits inside

typedef unsigned int u32;

// ---------------- device scratch ----------------
__device__ char  g_X8h[(size_t)NTOK * HDIM];
__device__ char  g_X8l[(size_t)NTOK * HDIM];
__device__ float g_rX[NTOK];
__device__ char  g_Wf8h[(size_t)NEXP * IDIM * HDIM];
__device__ char  g_Wf8l[(size_t)NEXP * IDIM * HDIM];
__device__ float g_rWf[NEXP * IDIM];
__device__ char  g_Wp8h[(size_t)NEXP * HDIM * IDIM];
__device__ char  g_Wp8l[(size_t)NEXP * HDIM * IDIM];
__device__ float g_rWp[NEXP * HDIM];
__device__ float g_H1f[(size_t)NSLOT * IDIM];
__device__ char  g_H18h[(size_t)NSLOT * IDIM];
__device__ char  g_H18l[(size_t)NSLOT * IDIM];
__device__ float g_rH1[NSLOT];
__device__ u32   g_rowmaxH1[NSLOT];
__device__ float g_Y2[(size_t)NSLOT * HDIM];
__device__ int   g_perm[NSLOT];
__device__ float g_wt[NSLOT];
__device__ int   g_slot[NSLOT];
__device__ int   g_te[NSLOT];
__device__ float g_twt[NSLOT];
__device__ int   g_counts[NEXP];
__device__ int   g_offsets[NEXP];
__device__ int   g_cursors[NEXP];
__device__ int   g_numTiles;
__device__ int   g_tileE[MAXT];
__device__ int   g_tileRow0[MAXT];
__device__ int   g_tileRows[MAXT];

// ---------------- cp.async helpers ----------------
__device__ __forceinline__ u32 smem_u32(const void* p) {
    u32 a;
    asm("{ .reg .u64 t; cvta.to.shared.u64 t, %1; cvt.u32.u64 %0, t; }" : "=r"(a) : "l"(p));
    return a;
}
__device__ __forceinline__ void cpa16(u32 dst, const void* src, u32 srcsz) {
    asm volatile("cp.async.cg.shared.global [%0], [%1], 16, %2;"
                 :: "r"(dst), "l"(src), "r"(srcsz) : "memory");
}
__device__ __forceinline__ void cpa_commit() {
    asm volatile("cp.async.commit_group;" ::: "memory");
}
template <int N>
__device__ __forceinline__ void cpa_wait() {
    asm volatile("cp.async.wait_group %0;" :: "n"(N) : "memory");
}

// ---------------- small kernels ----------------
__global__ void k_init() {
    int i = blockIdx.x * blockDim.x + threadIdx.x;
    if (i < NEXP) { g_counts[i] = 0; g_cursors[i] = 0; }
    for (int r = i; r < NSLOT; r += gridDim.x * blockDim.x) g_rowmaxH1[r] = 0u;
}

// per-row two-level int8 quantization: x ~= (h + l/256) * (rowmax/127)
__global__ void k_quant(const float* __restrict__ src, char* __restrict__ h8,
                        char* __restrict__ l8, float* __restrict__ rcp, int kdim) {
    int row = blockIdx.x, tid = threadIdx.x;
    const float4* p = (const float4*)(src + (size_t)row * kdim);
    int n4 = kdim >> 2;
    float mx = 0.f;
    for (int i = tid; i < n4; i += blockDim.x) {
        float4 v = p[i];
        mx = fmaxf(mx, fmaxf(fmaxf(fabsf(v.x), fabsf(v.y)), fmaxf(fabsf(v.z), fabsf(v.w))));
    }
    __shared__ float wmax[8];
#pragma unroll
    for (int o = 16; o; o >>= 1) mx = fmaxf(mx, __shfl_xor_sync(~0u, mx, o));
    if ((tid & 31) == 0) wmax[tid >> 5] = mx;
    __syncthreads();
    float q = fmaxf(fmaxf(fmaxf(wmax[0], wmax[1]), fmaxf(wmax[2], wmax[3])),
                    fmaxf(fmaxf(wmax[4], wmax[5]), fmaxf(wmax[6], wmax[7])));
    float s = (q > 0.f) ? 127.f / q : 0.f;
    if (tid == 0) rcp[row] = (q > 0.f) ? q / 127.f : 0.f;
    char4* hp = (char4*)(h8 + (size_t)row * kdim);
    char4* lp = (char4*)(l8 + (size_t)row * kdim);
    for (int i = tid; i < n4; i += blockDim.x) {
        float4 v = p[i];
        float a[4] = {v.x, v.y, v.z, v.w};
        char hc[4], lc[4];
#pragma unroll
        for (int c = 0; c < 4; c++) {
            float xs = a[c] * s;
            float hh = rintf(xs);
            float ll = fminf(rintf((xs - hh) * 256.f), 127.f);
            hc[c] = (char)(int)hh; lc[c] = (char)(int)ll;
        }
        hp[i] = make_char4(hc[0], hc[1], hc[2], hc[3]);
        lp[i] = make_char4(lc[0], lc[1], lc[2], lc[3]);
    }
}

// quantize H1 rows using precomputed row max (atomicMax from GEMM1 epilogue)
__global__ void k_quantH1() {
    int row = blockIdx.x, tid = threadIdx.x;
    float q = __uint_as_float(g_rowmaxH1[row]);
    float s = (q > 0.f) ? 127.f / q : 0.f;
    if (tid == 0) g_rH1[row] = (q > 0.f) ? q / 127.f : 0.f;
    const float4* p = (const float4*)(g_H1f + (size_t)row * IDIM);
    char4* hp = (char4*)(g_H18h + (size_t)row * IDIM);
    char4* lp = (char4*)(g_H18l + (size_t)row * IDIM);
    for (int i = tid; i < IDIM / 4; i += blockDim.x) {
        float4 v = p[i];
        float a[4] = {v.x, v.y, v.z, v.w};
        char hc[4], lc[4];
#pragma unroll
        for (int c = 0; c < 4; c++) {
            float xs = a[c] * s;
            float hh = rintf(xs);
            float ll = fminf(rintf((xs - hh) * 256.f), 127.f);
            hc[c] = (char)(int)hh; lc[c] = (char)(int)ll;
        }
        hp[i] = make_char4(hc[0], hc[1], hc[2], hc[3]);
        lp[i] = make_char4(lc[0], lc[1], lc[2], lc[3]);
    }
}

__global__ void k_router(const float* __restrict__ X, const float* __restrict__ Wg,
                         float* __restrict__ logits, int write_logits) {
    int warp = threadIdx.x >> 5, lane = threadIdx.x & 31;
    int t = blockIdx.x * (blockDim.x >> 5) + warp;
    if (t >= NTOK) return;
    const float* xp = X + (size_t)t * HDIM;
    float acc[NEXP];
#pragma unroll
    for (int e = 0; e < NEXP; e++) acc[e] = 0.f;
    for (int k = lane; k < HDIM; k += 32) {
        float xv = __ldg(xp + k);
#pragma unroll
        for (int e = 0; e < NEXP; e++) acc[e] = fmaf(xv, __ldg(Wg + e * HDIM + k), acc[e]);
    }
#pragma unroll
    for (int e = 0; e < NEXP; e++) {
        acc[e] += __shfl_xor_sync(0xffffffffu, acc[e], 16);
        acc[e] += __shfl_xor_sync(0xffffffffu, acc[e], 8);
        acc[e] += __shfl_xor_sync(0xffffffffu, acc[e], 4);
        acc[e] += __shfl_xor_sync(0xffffffffu, acc[e], 2);
        acc[e] += __shfl_xor_sync(0xffffffffu, acc[e], 1);
    }
    if (lane == 0) {
        if (write_logits) {
#pragma unroll
            for (int e = 0; e < NEXP; e++) logits[(size_t)t * NEXP + e] = acc[e];
        }
        int i0 = 0;
#pragma unroll
        for (int e = 1; e < NEXP; e++) if (acc[e] > acc[i0]) i0 = e;
        int i1 = (i0 == 0) ? 1 : 0;
#pragma unroll
        for (int e = 0; e < NEXP; e++) if (e != i1 && e != i0 && acc[e] > acc[i1]) i1 = e;
        float d  = expf(acc[i1] - acc[i0]);
        float w0 = 1.f / (1.f + d);
        g_te[2*t] = i0;   g_twt[2*t] = w0;
        g_te[2*t+1] = i1; g_twt[2*t+1] = 1.f - w0;
        atomicAdd(&g_counts[i0], 1);
        atomicAdd(&g_counts[i1], 1);
    }
}

__global__ void k_scan() {
    int off = 0, t = 0;
    for (int e = 0; e < NEXP; e++) {
        g_offsets[e] = off;
        int c = g_counts[e];
        for (int r = 0; r < c; r += BM) {
            g_tileE[t] = e; g_tileRow0[t] = off + r;
            g_tileRows[t] = (c - r < BM) ? (c - r) : BM;
            t++;
        }
        off += c;
    }
    g_numTiles = t;
}

__global__ void k_scatter() {
    int t = blockIdx.x * blockDim.x + threadIdx.x;
    if (t >= NTOK) return;
#pragma unroll
    for (int s = 0; s < 2; s++) {
        int e = g_te[2*t + s];
        int pos = g_offsets[e] + atomicAdd(&g_cursors[e], 1);
        g_perm[pos] = t;
        g_wt[pos] = g_twt[2*t + s];
        g_slot[2*t + s] = pos;
    }
}

// ---------------- async chunk issue: 4 int8 tiles, 128 rows x 64 B each ----------------
template <bool GATHER>
__device__ __forceinline__ void issue_chunk(
    u32 stg, int tid, int k0,
    const char* __restrict__ Ah, const char* __restrict__ Al, size_t a_stride,
    const int* rowTok, int rows,
    const char* __restrict__ Bh, const char* __restrict__ Bl, size_t b_stride)
{
    // 512 threads x 1 unit per tile: u=tid -> m = u>>2, kb = (u&3)*16
    int m = tid >> 2, kb = (tid & 3) * 16;
    u32 so = stg + (u32)(m * APITCH + kb);
    u32 sz; int row;
    if (GATHER) {
        int tok = rowTok[m];
        sz  = (tok >= 0) ? 16u : 0u;
        row = (tok >= 0) ? tok : 0;
    } else {
        sz  = (m < rows) ? 16u : 0u;
        row = (m < rows) ? m : 0;
    }
    size_t ao = (size_t)row * a_stride + k0 + kb;
    cpa16(so + OFF_AH, Ah + ao, sz);
    cpa16(so + OFF_AL, Al + ao, sz);
    size_t bo = (size_t)m * b_stride + k0 + kb;
    cpa16(so + OFF_BH, Bh + bo, 16u);
    cpa16(so + OFF_BL, Bl + bo, 16u);
}

// ---------------- int8 wmma GEMM core: 3-stage cp.async pipeline ----------------
// 16 warps: warp tile 32x32 (wm=wid&3 -> m, wn=wid>>2 -> n).
// acc_main += Ah*Bh ; acc_cross += Ah*Bl + Al*Bh ; (ll dropped)
template <bool GATHER>
__device__ __forceinline__ void gemm_tile_i8(
    char* smem, u32 sb, int tid,
    const char* __restrict__ Ah, const char* __restrict__ Al, size_t a_stride,
    const int* rowTok, int rows,
    const char* __restrict__ Bh, const char* __restrict__ Bl, size_t b_stride,
    int kdim,
    wmma::fragment<wmma::accumulator, 16, 16, 16, int> (&accm)[2][2],
    wmma::fragment<wmma::accumulator, 16, 16, 16, int> (&accx)[2][2])
{
    int wid = tid >> 5;
    int wm = wid & 3, wn = wid >> 2;

#pragma unroll
    for (int i = 0; i < 2; i++)
#pragma unroll
        for (int j = 0; j < 2; j++) { wmma::fill_fragment(accm[i][j], 0); wmma::fill_fragment(accx[i][j], 0); }

    int nch = kdim / BK;
    issue_chunk<GATHER>(sb + SM_STG0, tid, 0, Ah, Al, a_stride, rowTok, rows, Bh, Bl, b_stride);
    cpa_commit();
    issue_chunk<GATHER>(sb + SM_STG0 + STG_SZ, tid, BK, Ah, Al, a_stride, rowTok, rows, Bh, Bl, b_stride);
    cpa_commit();

    for (int ch = 0; ch < nch; ch++) {
        if (ch + 2 < nch) {
            issue_chunk<GATHER>(sb + SM_STG0 + ((ch + 2) % NSTAGE) * STG_SZ, tid, (ch + 2) * BK,
                                Ah, Al, a_stride, rowTok, rows, Bh, Bl, b_stride);
            cpa_commit();
            cpa_wait<2>();
        } else if (ch + 1 < nch) {
            cpa_wait<1>();
        } else {
            cpa_wait<0>();
        }
        __syncthreads();

        char* stg = smem + SM_STG0 + (ch % NSTAGE) * STG_SZ;
        const signed char* As_h = (const signed char*)(stg + OFF_AH);
        const signed char* As_l = (const signed char*)(stg + OFF_AL);
        const signed char* Bs_h = (const signed char*)(stg + OFF_BH);
        const signed char* Bs_l = (const signed char*)(stg + OFF_BL);

#pragma unroll
        for (int ks = 0; ks < 4; ks++) {
            wmma::fragment<wmma::matrix_b, 16, 16, 16, signed char, wmma::col_major> bh[2], bl[2];
#pragma unroll
            for (int j = 0; j < 2; j++) {
                int n = wn * 32 + j * 16;
                wmma::load_matrix_sync(bh[j], Bs_h + (size_t)n * APITCH + ks * 16, APITCH);
                wmma::load_matrix_sync(bl[j], Bs_l + (size_t)n * APITCH + ks * 16, APITCH);
            }
#pragma unroll
            for (int i = 0; i < 2; i++) {
                int m = wm * 32 + i * 16;
                wmma::fragment<wmma::matrix_a, 16, 16, 16, signed char, wmma::row_major> ah, al;
                wmma::load_matrix_sync(ah, As_h + (size_t)m * APITCH + ks * 16, APITCH);
                wmma::load_matrix_sync(al, As_l + (size_t)m * APITCH + ks * 16, APITCH);
#pragma unroll
                for (int j = 0; j < 2; j++) {
                    wmma::mma_sync(accm[i][j], ah, bh[j], accm[i][j]);
                    wmma::mma_sync(accx[i][j], ah, bl[j], accx[i][j]);
                    wmma::mma_sync(accx[i][j], al, bh[j], accx[i][j]);
                }
            }
        }
        __syncthreads();
    }
}

// ---------------- GEMM1: H1f = gelu(gather(X8) @ Wf8[e]^T), + row max ----------------
__global__ __launch_bounds__(512, 1) void k_gemm1(int) {
    int tile = blockIdx.x;
    if (tile >= g_numTiles) return;
    int e = g_tileE[tile], row0 = g_tileRow0[tile], rows = g_tileRows[tile];
    int col0 = blockIdx.y * BN;

    extern __shared__ char smem[];
    u32 sb = smem_u32(smem);
    int tid = threadIdx.x, wid = tid >> 5;
    int wm = wid & 3, wn = wid >> 2;

    int* rowTok = (int*)(smem + SM_ROWTOK);
    float* rowSc = (float*)(smem + SM_ROWSC);
    float* colSc = (float*)(smem + SM_COLSC);
    if (tid < BM) {
        int tok = (tid < rows) ? g_perm[row0 + tid] : -1;
        rowTok[tid] = tok;
        rowSc[tid] = (tok >= 0) ? g_rX[tok] : 0.f;
        colSc[tid] = g_rWf[e * IDIM + col0 + tid];
    }
    __syncthreads();

    wmma::fragment<wmma::accumulator, 16, 16, 16, int> accm[2][2], accx[2][2];
    const char* Bh = g_Wf8h + ((size_t)e * IDIM + col0) * HDIM;
    const char* Bl = g_Wf8l + ((size_t)e * IDIM + col0) * HDIM;
    gemm_tile_i8<true>(smem, sb, tid, g_X8h, g_X8l, HDIM, rowTok, rows, Bh, Bl, HDIM, HDIM, accm, accx);

    // combine int accs -> float frag -> stage
    float* st = (float*)(smem + SM_STG0);
    __syncthreads();
#pragma unroll
    for (int i = 0; i < 2; i++)
#pragma unroll
        for (int j = 0; j < 2; j++) {
            wmma::fragment<wmma::accumulator, 16, 16, 16, float> f;
#pragma unroll
            for (int k = 0; k < f.num_elements; k++)
                f.x[k] = (float)accm[i][j].x[k] + (float)accx[i][j].x[k] * 0.00390625f;
            wmma::store_matrix_sync(st + (size_t)(wm * 32 + i * 16) * SPITCH + wn * 32 + j * 16,
                                    f, SPITCH, wmma::mem_row_major);
        }
    __syncthreads();
    for (int u = tid; u < 128 * 16; u += 512) {   // 8 cols per unit
        int m = u >> 4, q = (u & 15) * 8;
        if (m < rows) {
            float sc = rowSc[m];
            float g8[8];
            float amax = 0.f;
#pragma unroll
            for (int c = 0; c < 8; c++) {
                float v = st[(size_t)m * SPITCH + q + c] * sc * colSc[q + c];
                float g = 0.5f * v * (1.f + erff(v * 0.70710678118654752f));
                g8[c] = g;
                amax = fmaxf(amax, fabsf(g));
            }
            size_t o = (size_t)(row0 + m) * IDIM + col0 + q;
            *(float4*)(g_H1f + o)     = make_float4(g8[0], g8[1], g8[2], g8[3]);
            *(float4*)(g_H1f + o + 4) = make_float4(g8[4], g8[5], g8[6], g8[7]);
            atomicMax(&g_rowmaxH1[row0 + m], __float_as_uint(amax));
        }
    }
}

// ---------------- GEMM2: Y2 = H18 @ Wp8[e]^T ----------------
__global__ __launch_bounds__(512, 1) void k_gemm2(int) {
    int tile = blockIdx.x;
    if (tile >= g_numTiles) return;
    int e = g_tileE[tile], row0 = g_tileRow0[tile], rows = g_tileRows[tile];
    int col0 = blockIdx.y * BN;

    extern __shared__ char smem[];
    u32 sb = smem_u32(smem);
    int tid = threadIdx.x, wid = tid >> 5;
    int wm = wid & 3, wn = wid >> 2;

    float* rowSc = (float*)(smem + SM_ROWSC);
    float* colSc = (float*)(smem + SM_COLSC);
    if (tid < BM) {
        rowSc[tid] = (tid < rows) ? g_rH1[row0 + tid] : 0.f;
        colSc[tid] = g_rWp[e * HDIM + col0 + tid];
    }
    __syncthreads();

    wmma::fragment<wmma::accumulator, 16, 16, 16, int> accm[2][2], accx[2][2];
    const char* Ah = g_H18h + (size_t)row0 * IDIM;
    const char* Al = g_H18l + (size_t)row0 * IDIM;
    const char* Bh = g_Wp8h + ((size_t)e * HDIM + col0) * IDIM;
    const char* Bl = g_Wp8l + ((size_t)e * HDIM + col0) * IDIM;
    gemm_tile_i8<false>(smem, sb, tid, Ah, Al, IDIM, nullptr, rows, Bh, Bl, IDIM, IDIM, accm, accx);

    float* st = (float*)(smem + SM_STG0);
    __syncthreads();
#pragma unroll
    for (int i = 0; i < 2; i++)
#pragma unroll
        for (int j = 0; j < 2; j++) {
            wmma::fragment<wmma::accumulator, 16, 16, 16, float> f;
#pragma unroll
            for (int k = 0; k < f.num_elements; k++)
                f.x[k] = (float)accm[i][j].x[k] + (float)accx[i][j].x[k] * 0.00390625f;
            wmma::store_matrix_sync(st + (size_t)(wm * 32 + i * 16) * SPITCH + wn * 32 + j * 16,
                                    f, SPITCH, wmma::mem_row_major);
        }
    __syncthreads();
    for (int u = tid; u < 128 * 32; u += 512) {   // 4 cols per unit
        int m = u >> 5, q = (u & 31) * 4;
        if (m < rows) {
            float sc = rowSc[m];
            float4 v;
            v.x = st[(size_t)m * SPITCH + q + 0] * sc * colSc[q + 0];
            v.y = st[(size_t)m * SPITCH + q + 1] * sc * colSc[q + 1];
            v.z = st[(size_t)m * SPITCH + q + 2] * sc * colSc[q + 2];
            v.w = st[(size_t)m * SPITCH + q + 3] * sc * colSc[q + 3];
            *(float4*)(g_Y2 + (size_t)(row0 + m) * HDIM + col0 + q) = v;
        }
    }
}

// ---------------- combine ----------------
__global__ void k_combine(float* __restrict__ out) {
    int i4 = blockIdx.x * blockDim.x + threadIdx.x;
    if (i4 >= NTOK * (HDIM / 4)) return;
    int t = i4 / (HDIM / 4), h4 = i4 % (HDIM / 4);
    int p0 = g_slot[2*t], p1 = g_slot[2*t + 1];
    float w0 = g_wt[p0], w1 = g_wt[p1];
    float4 a = *(const float4*)(g_Y2 + (size_t)p0 * HDIM + h4 * 4);
    float4 b = *(const float4*)(g_Y2 + (size_t)p1 * HDIM + h4 * 4);
    float4 o;
    o.x = fmaf(w0, a.x, w1 * b.x);
    o.y = fmaf(w0, a.y, w1 * b.y);
    o.z = fmaf(w0, a.z, w1 * b.z);
    o.w = fmaf(w0, a.w, w1 * b.w);
    *((float4*)out + i4) = o;
}

// ---------------- launch ----------------
extern "C" void kernel_launch(void* const* d_in, const int* in_sizes, int n_in,
                              void* d_out, int out_size) {
    const float* X     = (const float*)d_in[0];
    const float* Wg    = (const float*)d_in[1];
    const float* Wfc   = (const float*)d_in[2];
    const float* Wproj = (const float*)d_in[3];
    float* out = (float*)d_out;

    int write_logits = (out_size >= NTOK * HDIM + NTOK * NEXP) ? 1 : 0;
    float* logits = out + (size_t)NTOK * HDIM;

    static int attr_done = 0;
    if (!attr_done) {
        cudaFuncSetAttribute(k_gemm1, cudaFuncAttributeMaxDynamicSharedMemorySize, DSMEM);
        cudaFuncSetAttribute(k_gemm2, cudaFuncAttributeMaxDynamicSharedMemorySize, DSMEM);
        attr_done = 1;
    }

    char *x8h, *x8l, *wf8h, *wf8l, *wp8h, *wp8l;
    float *rx, *rwf, *rwp;
    cudaGetSymbolAddress((void**)&x8h, g_X8h);   cudaGetSymbolAddress((void**)&x8l, g_X8l);
    cudaGetSymbolAddress((void**)&wf8h, g_Wf8h); cudaGetSymbolAddress((void**)&wf8l, g_Wf8l);
    cudaGetSymbolAddress((void**)&wp8h, g_Wp8h); cudaGetSymbolAddress((void**)&wp8l, g_Wp8l);
    cudaGetSymbolAddress((void**)&rx, g_rX);
    cudaGetSymbolAddress((void**)&rwf, g_rWf);
    cudaGetSymbolAddress((void**)&rwp, g_rWp);

    k_init<<<64, 256>>>();
    k_quant<<<NTOK, 256>>>(X, x8h, x8l, rx, HDIM);
    k_quant<<<NEXP * IDIM, 256>>>(Wfc, wf8h, wf8l, rwf, HDIM);
    k_quant<<<NEXP * HDIM, 256>>>(Wproj, wp8h, wp8l, rwp, IDIM);
    k_router<<<NTOK / 8, 256>>>(X, Wg, logits, write_logits);
    k_scan<<<1, 1>>>();
    k_scatter<<<NTOK / 256, 256>>>();
    k_gemm1<<<dim3(MAXT, IDIM / BN), 512, DSMEM>>>(0);
    k_quantH1<<<NSLOT, 256>>>();
    k_gemm2<<<dim3(MAXT, HDIM / BN), 512, DSMEM>>>(0);
    k_combine<<<(NTOK * (HDIM / 4) + 255) / 256, 256>>>(out);
}

// round 12
// speedup vs baseline: 3.9459x; 3.9459x over previous
#include <cuda_runtime.h>
#include <cuda_bf16.h>
#include <mma.h>
#include <math.h>

using namespace nvcuda;

// ---------------- problem constants ----------------
#define NTOK 8192
#define HDIM 1024
#define IDIM 2048
#define NEXP 8
#define NSLOT (NTOK*2)

#define BM 128
#define BN 256            // wide N tile: 8 warps x (64x64) warp tiles
#define BK 32
#define MAXT 136

#define PITCH 40          // bf16 elems; 80B row stride -> conflict-free ldmatrix
#define SPITCH 260        // float stage pitch (epilogue, 256+4)

// smem layout (bytes)
#define SM_ROWTOK 0       // 128 ints
#define SM_STG0   1024
#define A_TILE_B  (128*PITCH*2)        // 10240
#define B_TILE_B  (256*PITCH*2)        // 20480
#define OFF_AH 0
#define OFF_AL A_TILE_B
#define OFF_BH (2*A_TILE_B)
#define OFF_BL (2*A_TILE_B + B_TILE_B)
#define STG_SZ (2*A_TILE_B + 2*B_TILE_B)   // 61440
#define NSTAGE 3
#define DSMEM (SM_STG0 + NSTAGE*STG_SZ)    // 185344; epilogue 128*260*4=133120 fits

typedef unsigned int u32;

// ---------------- device scratch ----------------
__device__ __nv_bfloat16 g_Xhi[(size_t)NTOK * HDIM];
__device__ __nv_bfloat16 g_Xlo[(size_t)NTOK * HDIM];
__device__ __nv_bfloat16 g_Wfh[(size_t)NEXP * IDIM * HDIM];
__device__ __nv_bfloat16 g_Wfl[(size_t)NEXP * IDIM * HDIM];
__device__ __nv_bfloat16 g_Wph[(size_t)NEXP * HDIM * IDIM];
__device__ __nv_bfloat16 g_Wpl[(size_t)NEXP * HDIM * IDIM];
__device__ __nv_bfloat16 g_H1h[(size_t)NSLOT * IDIM];
__device__ __nv_bfloat16 g_H1l[(size_t)NSLOT * IDIM];
__device__ float g_Y2[(size_t)NSLOT * HDIM];
__device__ int   g_perm[NSLOT];
__device__ float g_wt[NSLOT];
__device__ int   g_slot[NSLOT];
__device__ int   g_te[NSLOT];
__device__ float g_twt[NSLOT];
__device__ int   g_counts[NEXP];
__device__ int   g_offsets[NEXP];
__device__ int   g_cursors[NEXP];
__device__ int   g_numTiles;
__device__ int   g_tileE[MAXT];
__device__ int   g_tileRow0[MAXT];
__device__ int   g_tileRows[MAXT];

// ---------------- cp.async helpers ----------------
__device__ __forceinline__ u32 smem_u32(const void* p) {
    u32 a;
    asm("{ .reg .u64 t; cvta.to.shared.u64 t, %1; cvt.u32.u64 %0, t; }" : "=r"(a) : "l"(p));
    return a;
}
__device__ __forceinline__ void cpa16(u32 dst, const void* src, u32 srcsz) {
    asm volatile("cp.async.cg.shared.global [%0], [%1], 16, %2;"
                 :: "r"(dst), "l"(src), "r"(srcsz) : "memory");
}
__device__ __forceinline__ void cpa_commit() {
    asm volatile("cp.async.commit_group;" ::: "memory");
}
template <int N>
__device__ __forceinline__ void cpa_wait() {
    asm volatile("cp.async.wait_group %0;" :: "n"(N) : "memory");
}

// ---------------- small kernels ----------------
__global__ void k_init() {
    int i = threadIdx.x;
    if (i < NEXP) { g_counts[i] = 0; g_cursors[i] = 0; }
}

__global__ void k_split(const float* __restrict__ s, __nv_bfloat16* __restrict__ hi,
                        __nv_bfloat16* __restrict__ lo, int n4) {
    int i = blockIdx.x * blockDim.x + threadIdx.x;
    if (i >= n4) return;
    float4 v = ((const float4*)s)[i];
    __nv_bfloat16 h0 = __float2bfloat16(v.x), h1 = __float2bfloat16(v.y);
    __nv_bfloat16 h2 = __float2bfloat16(v.z), h3 = __float2bfloat16(v.w);
    __nv_bfloat16 l0 = __float2bfloat16(v.x - __bfloat162float(h0));
    __nv_bfloat16 l1 = __float2bfloat16(v.y - __bfloat162float(h1));
    __nv_bfloat16 l2 = __float2bfloat16(v.z - __bfloat162float(h2));
    __nv_bfloat16 l3 = __float2bfloat16(v.w - __bfloat162float(h3));
    uint2 ph, pl;
    ph.x = (u32)__bfloat16_as_ushort(h0) | ((u32)__bfloat16_as_ushort(h1) << 16);
    ph.y = (u32)__bfloat16_as_ushort(h2) | ((u32)__bfloat16_as_ushort(h3) << 16);
    pl.x = (u32)__bfloat16_as_ushort(l0) | ((u32)__bfloat16_as_ushort(l1) << 16);
    pl.y = (u32)__bfloat16_as_ushort(l2) | ((u32)__bfloat16_as_ushort(l3) << 16);
    ((uint2*)hi)[i] = ph;
    ((uint2*)lo)[i] = pl;
}

__global__ void k_router(const float* __restrict__ X, const float* __restrict__ Wg,
                         float* __restrict__ logits, int write_logits) {
    int warp = threadIdx.x >> 5, lane = threadIdx.x & 31;
    int t = blockIdx.x * (blockDim.x >> 5) + warp;
    if (t >= NTOK) return;
    const float* xp = X + (size_t)t * HDIM;
    float acc[NEXP];
#pragma unroll
    for (int e = 0; e < NEXP; e++) acc[e] = 0.f;
    for (int k = lane; k < HDIM; k += 32) {
        float xv = __ldg(xp + k);
#pragma unroll
        for (int e = 0; e < NEXP; e++) acc[e] = fmaf(xv, __ldg(Wg + e * HDIM + k), acc[e]);
    }
#pragma unroll
    for (int e = 0; e < NEXP; e++) {
        acc[e] += __shfl_xor_sync(0xffffffffu, acc[e], 16);
        acc[e] += __shfl_xor_sync(0xffffffffu, acc[e], 8);
        acc[e] += __shfl_xor_sync(0xffffffffu, acc[e], 4);
        acc[e] += __shfl_xor_sync(0xffffffffu, acc[e], 2);
        acc[e] += __shfl_xor_sync(0xffffffffu, acc[e], 1);
    }
    if (lane == 0) {
        if (write_logits) {
#pragma unroll
            for (int e = 0; e < NEXP; e++) logits[(size_t)t * NEXP + e] = acc[e];
        }
        int i0 = 0;
#pragma unroll
        for (int e = 1; e < NEXP; e++) if (acc[e] > acc[i0]) i0 = e;
        int i1 = (i0 == 0) ? 1 : 0;
#pragma unroll
        for (int e = 0; e < NEXP; e++) if (e != i1 && e != i0 && acc[e] > acc[i1]) i1 = e;
        float d  = expf(acc[i1] - acc[i0]);
        float w0 = 1.f / (1.f + d);
        g_te[2*t] = i0;   g_twt[2*t] = w0;
        g_te[2*t+1] = i1; g_twt[2*t+1] = 1.f - w0;
        atomicAdd(&g_counts[i0], 1);
        atomicAdd(&g_counts[i1], 1);
    }
}

__global__ void k_scan() {
    int off = 0, t = 0;
    for (int e = 0; e < NEXP; e++) {
        g_offsets[e] = off;
        int c = g_counts[e];
        for (int r = 0; r < c; r += BM) {
            g_tileE[t] = e; g_tileRow0[t] = off + r;
            g_tileRows[t] = (c - r < BM) ? (c - r) : BM;
            t++;
        }
        off += c;
    }
    g_numTiles = t;
}

__global__ void k_scatter() {
    int t = blockIdx.x * blockDim.x + threadIdx.x;
    if (t >= NTOK) return;
#pragma unroll
    for (int s = 0; s < 2; s++) {
        int e = g_te[2*t + s];
        int pos = g_offsets[e] + atomicAdd(&g_cursors[e], 1);
        g_perm[pos] = t;
        g_wt[pos] = g_twt[2*t + s];
        g_slot[2*t + s] = pos;
    }
}

// ---------------- async chunk issue: A 128x32, B 256x32 bf16 (hi+lo) ----------------
template <bool GATHER>
__device__ __forceinline__ void issue_chunk(
    u32 stg, int tid, int k0,
    const __nv_bfloat16* __restrict__ Ah, const __nv_bfloat16* __restrict__ Al,
    size_t a_stride, const int* rowTok, int rows,
    const __nv_bfloat16* __restrict__ Bh, const __nv_bfloat16* __restrict__ Bl,
    size_t b_stride)
{
    // A: 128 rows x 4 x 16B units = 512 units
#pragma unroll
    for (int t4 = 0; t4 < 2; t4++) {
        int u = tid + t4 * 256;
        int m = u >> 2, kq = u & 3;
        u32 so = stg + (u32)(m * PITCH + kq * 8) * 2;
        u32 sz; int row;
        if (GATHER) {
            int tok = rowTok[m];
            sz  = (tok >= 0) ? 16u : 0u;
            row = (tok >= 0) ? tok : 0;
        } else {
            sz  = (m < rows) ? 16u : 0u;
            row = (m < rows) ? m : 0;
        }
        size_t ao = (size_t)row * a_stride + k0 + kq * 8;
        cpa16(so + OFF_AH, Ah + ao, sz);
        cpa16(so + OFF_AL, Al + ao, sz);
    }
    // B: 256 rows x 4 x 16B units = 1024 units
#pragma unroll
    for (int t4 = 0; t4 < 4; t4++) {
        int u = tid + t4 * 256;
        int n = u >> 2, kq = u & 3;
        u32 so = stg + (u32)(n * PITCH + kq * 8) * 2;
        size_t bo = (size_t)n * b_stride + k0 + kq * 8;
        cpa16(so + OFF_BH, Bh + bo, 16u);
        cpa16(so + OFF_BL, Bl + bo, 16u);
    }
}

// ---------------- wmma GEMM core: 3-stage cp.async, 64x64 warp tiles ----------------
// 8 warps: wm = wid&1 (64 rows), wn = wid>>1 (64 cols). 3-term bf16 split.
template <bool GATHER>
__device__ __forceinline__ void gemm_tile(
    char* smem, u32 sb, int tid,
    const __nv_bfloat16* __restrict__ Ah, const __nv_bfloat16* __restrict__ Al,
    size_t a_stride, const int* rowTok, int rows,
    const __nv_bfloat16* __restrict__ Bh, const __nv_bfloat16* __restrict__ Bl,
    size_t b_stride, int kdim,
    wmma::fragment<wmma::accumulator, 16, 16, 16, float> (&acc)[4][4])
{
    int wid = tid >> 5;
    int wm = wid & 1, wn = wid >> 1;

#pragma unroll
    for (int i = 0; i < 4; i++)
#pragma unroll
        for (int j = 0; j < 4; j++) wmma::fill_fragment(acc[i][j], 0.f);

    int nch = kdim / BK;
    issue_chunk<GATHER>(sb + SM_STG0, tid, 0, Ah, Al, a_stride, rowTok, rows, Bh, Bl, b_stride);
    cpa_commit();
    issue_chunk<GATHER>(sb + SM_STG0 + STG_SZ, tid, BK, Ah, Al, a_stride, rowTok, rows, Bh, Bl, b_stride);
    cpa_commit();

    for (int ch = 0; ch < nch; ch++) {
        if (ch + 2 < nch) {
            issue_chunk<GATHER>(sb + SM_STG0 + ((ch + 2) % NSTAGE) * STG_SZ, tid, (ch + 2) * BK,
                                Ah, Al, a_stride, rowTok, rows, Bh, Bl, b_stride);
            cpa_commit();
            cpa_wait<2>();
        } else if (ch + 1 < nch) {
            cpa_wait<1>();
        } else {
            cpa_wait<0>();
        }
        __syncthreads();

        char* stg = smem + SM_STG0 + (ch % NSTAGE) * STG_SZ;
        const __nv_bfloat16* As_h = (const __nv_bfloat16*)(stg + OFF_AH);
        const __nv_bfloat16* As_l = (const __nv_bfloat16*)(stg + OFF_AL);
        const __nv_bfloat16* Bs_h = (const __nv_bfloat16*)(stg + OFF_BH);
        const __nv_bfloat16* Bs_l = (const __nv_bfloat16*)(stg + OFF_BL);

#pragma unroll
        for (int ks = 0; ks < 2; ks++) {
            // A frags once per ks: 4 hi + 4 lo (reused across all 4 j)
            wmma::fragment<wmma::matrix_a, 16, 16, 16, __nv_bfloat16, wmma::row_major> ah[4], al[4];
#pragma unroll
            for (int i = 0; i < 4; i++) {
                int m = wm * 64 + i * 16;
                wmma::load_matrix_sync(ah[i], As_h + (size_t)m * PITCH + ks * 16, PITCH);
                wmma::load_matrix_sync(al[i], As_l + (size_t)m * PITCH + ks * 16, PITCH);
            }
#pragma unroll
            for (int j = 0; j < 4; j++) {
                int n = wn * 64 + j * 16;
                wmma::fragment<wmma::matrix_b, 16, 16, 16, __nv_bfloat16, wmma::col_major> bh, bl;
                wmma::load_matrix_sync(bh, Bs_h + (size_t)n * PITCH + ks * 16, PITCH);
                wmma::load_matrix_sync(bl, Bs_l + (size_t)n * PITCH + ks * 16, PITCH);
#pragma unroll
                for (int i = 0; i < 4; i++) {
                    wmma::mma_sync(acc[i][j], ah[i], bh, acc[i][j]);
                    wmma::mma_sync(acc[i][j], ah[i], bl, acc[i][j]);
                    wmma::mma_sync(acc[i][j], al[i], bh, acc[i][j]);
                }
            }
        }
        __syncthreads();
    }
}

// ---------------- GEMM1: H1 = gelu(gather(X) @ Wfc[e]^T) ----------------
__global__ __launch_bounds__(256, 1) void k_gemm1(int) {
    int tile = blockIdx.x;
    if (tile >= g_numTiles) return;
    int e = g_tileE[tile], row0 = g_tileRow0[tile], rows = g_tileRows[tile];
    int col0 = blockIdx.y * BN;

    extern __shared__ char smem[];
    u32 sb = smem_u32(smem);
    int tid = threadIdx.x, wid = tid >> 5;
    int wm = wid & 1, wn = wid >> 1;

    int* rowTok = (int*)(smem + SM_ROWTOK);
    if (tid < BM) rowTok[tid] = (tid < rows) ? g_perm[row0 + tid] : -1;
    __syncthreads();

    wmma::fragment<wmma::accumulator, 16, 16, 16, float> acc[4][4];
    const __nv_bfloat16* Bh = g_Wfh + ((size_t)e * IDIM + col0) * HDIM;
    const __nv_bfloat16* Bl = g_Wfl + ((size_t)e * IDIM + col0) * HDIM;
    gemm_tile<true>(smem, sb, tid, g_Xhi, g_Xlo, HDIM, rowTok, rows, Bh, Bl, HDIM, HDIM, acc);

    float* st = (float*)(smem + SM_STG0);   // 128 x SPITCH floats
    __syncthreads();
#pragma unroll
    for (int i = 0; i < 4; i++)
#pragma unroll
        for (int j = 0; j < 4; j++)
            wmma::store_matrix_sync(st + (size_t)(wm * 64 + i * 16) * SPITCH
                                       + wn * 64 + j * 16,
                                    acc[i][j], SPITCH, wmma::mem_row_major);
    __syncthreads();
    for (int u = tid; u < 128 * 32; u += 256) {   // 8 bf16 cols per unit
        int m = u >> 5, q = (u & 31) * 8;
        if (m < rows) {
            __nv_bfloat16 h8[8], l8[8];
#pragma unroll
            for (int c = 0; c < 8; c++) {
                float v = st[(size_t)m * SPITCH + q + c];
                float g = 0.5f * v * (1.f + erff(v * 0.70710678118654752f));
                __nv_bfloat16 h = __float2bfloat16(g);
                h8[c] = h;
                l8[c] = __float2bfloat16(g - __bfloat162float(h));
            }
            size_t o = (size_t)(row0 + m) * IDIM + col0 + q;
            *(uint4*)(g_H1h + o) = *(const uint4*)h8;
            *(uint4*)(g_H1l + o) = *(const uint4*)l8;
        }
    }
}

// ---------------- GEMM2: Y2 = H1 @ Wproj[e]^T ----------------
__global__ __launch_bounds__(256, 1) void k_gemm2(int) {
    int tile = blockIdx.x;
    if (tile >= g_numTiles) return;
    int e = g_tileE[tile], row0 = g_tileRow0[tile], rows = g_tileRows[tile];
    int col0 = blockIdx.y * BN;

    extern __shared__ char smem[];
    u32 sb = smem_u32(smem);
    int tid = threadIdx.x, wid = tid >> 5;
    int wm = wid & 1, wn = wid >> 1;

    wmma::fragment<wmma::accumulator, 16, 16, 16, float> acc[4][4];
    const __nv_bfloat16* Ah = g_H1h + (size_t)row0 * IDIM;
    const __nv_bfloat16* Al = g_H1l + (size_t)row0 * IDIM;
    const __nv_bfloat16* Bh = g_Wph + ((size_t)e * HDIM + col0) * IDIM;
    const __nv_bfloat16* Bl = g_Wpl + ((size_t)e * HDIM + col0) * IDIM;
    gemm_tile<false>(smem, sb, tid, Ah, Al, IDIM, nullptr, rows, Bh, Bl, IDIM, IDIM, acc);

    float* st = (float*)(smem + SM_STG0);
    __syncthreads();
#pragma unroll
    for (int i = 0; i < 4; i++)
#pragma unroll
        for (int j = 0; j < 4; j++)
            wmma::store_matrix_sync(st + (size_t)(wm * 64 + i * 16) * SPITCH
                                       + wn * 64 + j * 16,
                                    acc[i][j], SPITCH, wmma::mem_row_major);
    __syncthreads();
    for (int u = tid; u < 128 * 64; u += 256) {   // 4 floats per unit
        int m = u >> 6, q = (u & 63) * 4;
        if (m < rows) {
            size_t o = (size_t)(row0 + m) * HDIM + col0 + q;
            *(uint4*)(g_Y2 + o) = *(const uint4*)(st + (size_t)m * SPITCH + q);
        }
    }
}

// ---------------- combine ----------------
__global__ void k_combine(float* __restrict__ out) {
    int i4 = blockIdx.x * blockDim.x + threadIdx.x;
    if (i4 >= NTOK * (HDIM / 4)) return;
    int t = i4 / (HDIM / 4), h4 = i4 % (HDIM / 4);
    int p0 = g_slot[2*t], p1 = g_slot[2*t + 1];
    float w0 = g_wt[p0], w1 = g_wt[p1];
    float4 a = *(const float4*)(g_Y2 + (size_t)p0 * HDIM + h4 * 4);
    float4 b = *(const float4*)(g_Y2 + (size_t)p1 * HDIM + h4 * 4);
    float4 o;
    o.x = fmaf(w0, a.x, w1 * b.x);
    o.y = fmaf(w0, a.y, w1 * b.y);
    o.z = fmaf(w0, a.z, w1 * b.z);
    o.w = fmaf(w0, a.w, w1 * b.w);
    *((float4*)out + i4) = o;
}

// ---------------- launch ----------------
extern "C" void kernel_launch(void* const* d_in, const int* in_sizes, int n_in,
                              void* d_out, int out_size) {
    const float* X     = (const float*)d_in[0];
    const float* Wg    = (const float*)d_in[1];
    const float* Wfc   = (const float*)d_in[2];
    const float* Wproj = (const float*)d_in[3];
    float* out = (float*)d_out;

    int write_logits = (out_size >= NTOK * HDIM + NTOK * NEXP) ? 1 : 0;
    float* logits = out + (size_t)NTOK * HDIM;

    static int attr_done = 0;
    if (!attr_done) {
        cudaFuncSetAttribute(k_gemm1, cudaFuncAttributeMaxDynamicSharedMemorySize, DSMEM);
        cudaFuncSetAttribute(k_gemm2, cudaFuncAttributeMaxDynamicSharedMemorySize, DSMEM);
        attr_done = 1;
    }

    __nv_bfloat16 *xh, *xl, *wfh, *wfl, *wph, *wpl;
    cudaGetSymbolAddress((void**)&xh,  g_Xhi);  cudaGetSymbolAddress((void**)&xl,  g_Xlo);
    cudaGetSymbolAddress((void**)&wfh, g_Wfh);  cudaGetSymbolAddress((void**)&wfl, g_Wfl);
    cudaGetSymbolAddress((void**)&wph, g_Wph);  cudaGetSymbolAddress((void**)&wpl, g_Wpl);

    k_init<<<1, 32>>>();
    {
        int n4 = NTOK * HDIM / 4;
        k_split<<<(n4 + 255) / 256, 256>>>(X, xh, xl, n4);
    }
    {
        int n4 = NEXP * IDIM * HDIM / 4;
        k_split<<<(n4 + 255) / 256, 256>>>(Wfc, wfh, wfl, n4);
        k_split<<<(n4 + 255) / 256, 256>>>(Wproj, wph, wpl, n4);
    }
    k_router<<<NTOK / 8, 256>>>(X, Wg, logits, write_logits);
    k_scan<<<1, 1>>>();
    k_scatter<<<NTOK / 256, 256>>>();
    k_gemm1<<<dim3(MAXT, IDIM / BN), 256, DSMEM>>>(0);
    k_gemm2<<<dim3(MAXT, HDIM / BN), 256, DSMEM>>>(0);
    k_combine<<<(NTOK * (HDIM / 4) + 255) / 256, 256>>>(out);
}

// round 13
// speedup vs baseline: 4.5314x; 1.1484x over previous
#include <cuda_runtime.h>
#include <cuda_fp16.h>
#include <mma.h>
#include <math.h>

using namespace nvcuda;

// ---------------- problem constants ----------------
#define NTOK 8192
#define HDIM 1024
#define IDIM 2048
#define NEXP 8
#define NSLOT (NTOK*2)

#define BM 128
#define BN 128
#define BK 32
#define MAXT 136

#define PITCH 40          // fp16 elems; 80B row stride -> conflict-free ldmatrix
#define SPITCH 132        // float stage pitch (epilogue)
#define LOSCALE 2048.0f
#define INV_LOSCALE 4.8828125e-4f

// double-buffered smem layout (bytes)
#define SM_ROWTOK 0
#define SM_STG0   1024
#define TILE_B    (128*PITCH*2)        // 10240 per operand tile
#define STG_SZ    (4*TILE_B)           // 40960 per stage (Ah,Al,Bh,Bl)
#define OFF_AH 0
#define OFF_AL (1*TILE_B)
#define OFF_BH (2*TILE_B)
#define OFF_BL (3*TILE_B)
#define DSMEM (SM_STG0 + 2*STG_SZ)     // 82944; epilogue float stage 67584 fits

typedef unsigned int u32;

// ---------------- device scratch ----------------
__device__ __half g_Xhi[(size_t)NTOK * HDIM];
__device__ __half g_Xlo[(size_t)NTOK * HDIM];     // scaled x2048
__device__ __half g_Wfh[(size_t)NEXP * IDIM * HDIM];
__device__ __half g_Wfl[(size_t)NEXP * IDIM * HDIM];
__device__ __half g_Wph[(size_t)NEXP * HDIM * IDIM];
__device__ __half g_Wpl[(size_t)NEXP * HDIM * IDIM];
__device__ __half g_H1h[(size_t)NSLOT * IDIM];
__device__ __half g_H1l[(size_t)NSLOT * IDIM];    // scaled x2048
__device__ float g_Y2[(size_t)NSLOT * HDIM];
__device__ int   g_perm[NSLOT];
__device__ float g_wt[NSLOT];
__device__ int   g_slot[NSLOT];
__device__ int   g_te[NSLOT];
__device__ float g_twt[NSLOT];
__device__ int   g_counts[NEXP];
__device__ int   g_offsets[NEXP];
__device__ int   g_cursors[NEXP];
__device__ int   g_numTiles;
__device__ int   g_tileE[MAXT];
__device__ int   g_tileRow0[MAXT];
__device__ int   g_tileRows[MAXT];

// ---------------- cp.async helpers ----------------
__device__ __forceinline__ u32 smem_u32(const void* p) {
    u32 a;
    asm("{ .reg .u64 t; cvta.to.shared.u64 t, %1; cvt.u32.u64 %0, t; }" : "=r"(a) : "l"(p));
    return a;
}
__device__ __forceinline__ void cpa16(u32 dst, const void* src, u32 srcsz) {
    asm volatile("cp.async.cg.shared.global [%0], [%1], 16, %2;"
                 :: "r"(dst), "l"(src), "r"(srcsz) : "memory");
}
__device__ __forceinline__ void cpa_commit() {
    asm volatile("cp.async.commit_group;" ::: "memory");
}
template <int N>
__device__ __forceinline__ void cpa_wait() {
    asm volatile("cp.async.wait_group %0;" :: "n"(N) : "memory");
}

// ---------------- small kernels ----------------
__global__ void k_init() {
    int i = threadIdx.x;
    if (i < NEXP) { g_counts[i] = 0; g_cursors[i] = 0; }
}

// fp16 two-level split: x = h + (l/2048), h/l fp16
__global__ void k_split(const float* __restrict__ s, __half* __restrict__ hi,
                        __half* __restrict__ lo, int n4) {
    int i = blockIdx.x * blockDim.x + threadIdx.x;
    if (i >= n4) return;
    float4 v = ((const float4*)s)[i];
    __half h0 = __float2half(v.x), h1 = __float2half(v.y);
    __half h2 = __float2half(v.z), h3 = __float2half(v.w);
    __half l0 = __float2half((v.x - __half2float(h0)) * LOSCALE);
    __half l1 = __float2half((v.y - __half2float(h1)) * LOSCALE);
    __half l2 = __float2half((v.z - __half2float(h2)) * LOSCALE);
    __half l3 = __float2half((v.w - __half2float(h3)) * LOSCALE);
    uint2 ph, pl;
    ph.x = (u32)__half_as_ushort(h0) | ((u32)__half_as_ushort(h1) << 16);
    ph.y = (u32)__half_as_ushort(h2) | ((u32)__half_as_ushort(h3) << 16);
    pl.x = (u32)__half_as_ushort(l0) | ((u32)__half_as_ushort(l1) << 16);
    pl.y = (u32)__half_as_ushort(l2) | ((u32)__half_as_ushort(l3) << 16);
    ((uint2*)hi)[i] = ph;
    ((uint2*)lo)[i] = pl;
}

__global__ void k_router(const float* __restrict__ X, const float* __restrict__ Wg,
                         float* __restrict__ logits, int write_logits) {
    int warp = threadIdx.x >> 5, lane = threadIdx.x & 31;
    int t = blockIdx.x * (blockDim.x >> 5) + warp;
    if (t >= NTOK) return;
    const float* xp = X + (size_t)t * HDIM;
    float acc[NEXP];
#pragma unroll
    for (int e = 0; e < NEXP; e++) acc[e] = 0.f;
    for (int k = lane; k < HDIM; k += 32) {
        float xv = __ldg(xp + k);
#pragma unroll
        for (int e = 0; e < NEXP; e++) acc[e] = fmaf(xv, __ldg(Wg + e * HDIM + k), acc[e]);
    }
#pragma unroll
    for (int e = 0; e < NEXP; e++) {
        acc[e] += __shfl_xor_sync(0xffffffffu, acc[e], 16);
        acc[e] += __shfl_xor_sync(0xffffffffu, acc[e], 8);
        acc[e] += __shfl_xor_sync(0xffffffffu, acc[e], 4);
        acc[e] += __shfl_xor_sync(0xffffffffu, acc[e], 2);
        acc[e] += __shfl_xor_sync(0xffffffffu, acc[e], 1);
    }
    if (lane == 0) {
        if (write_logits) {
#pragma unroll
            for (int e = 0; e < NEXP; e++) logits[(size_t)t * NEXP + e] = acc[e];
        }
        int i0 = 0;
#pragma unroll
        for (int e = 1; e < NEXP; e++) if (acc[e] > acc[i0]) i0 = e;
        int i1 = (i0 == 0) ? 1 : 0;
#pragma unroll
        for (int e = 0; e < NEXP; e++) if (e != i1 && e != i0 && acc[e] > acc[i1]) i1 = e;
        float d  = expf(acc[i1] - acc[i0]);
        float w0 = 1.f / (1.f + d);
        g_te[2*t] = i0;   g_twt[2*t] = w0;
        g_te[2*t+1] = i1; g_twt[2*t+1] = 1.f - w0;
        atomicAdd(&g_counts[i0], 1);
        atomicAdd(&g_counts[i1], 1);
    }
}

__global__ void k_scan() {
    int off = 0, t = 0;
    for (int e = 0; e < NEXP; e++) {
        g_offsets[e] = off;
        int c = g_counts[e];
        for (int r = 0; r < c; r += BM) {
            g_tileE[t] = e; g_tileRow0[t] = off + r;
            g_tileRows[t] = (c - r < BM) ? (c - r) : BM;
            t++;
        }
        off += c;
    }
    g_numTiles = t;
}

__global__ void k_scatter() {
    int t = blockIdx.x * blockDim.x + threadIdx.x;
    if (t >= NTOK) return;
#pragma unroll
    for (int s = 0; s < 2; s++) {
        int e = g_te[2*t + s];
        int pos = g_offsets[e] + atomicAdd(&g_cursors[e], 1);
        g_perm[pos] = t;
        g_wt[pos] = g_twt[2*t + s];
        g_slot[2*t + s] = pos;
    }
}

// ---------------- async chunk issue: 4 fp16 tiles, 128x32 each ----------------
template <bool GATHER>
__device__ __forceinline__ void issue_chunk(
    u32 stg, int tid, int k0,
    const __half* __restrict__ Ah, const __half* __restrict__ Al,
    size_t a_stride, const int* rowTok, int rows,
    const __half* __restrict__ Bh, const __half* __restrict__ Bl,
    size_t b_stride)
{
#pragma unroll
    for (int t4 = 0; t4 < 2; t4++) {
        int u = tid + t4 * 256;          // 0..511 -> 128 rows x 4 16B units
        int m = u >> 2, kb = (u & 3) * 8;
        u32 so = stg + (u32)(m * PITCH + kb) * 2;
        u32 sz; int row;
        if (GATHER) {
            int tok = rowTok[m];
            sz  = (tok >= 0) ? 16u : 0u;
            row = (tok >= 0) ? tok : 0;
        } else {
            sz  = (m < rows) ? 16u : 0u;
            row = (m < rows) ? m : 0;
        }
        size_t ao = (size_t)row * a_stride + k0 + kb;
        cpa16(so + OFF_AH, Ah + ao, sz);
        cpa16(so + OFF_AL, Al + ao, sz);
        size_t bo = (size_t)m * b_stride + k0 + kb;
        cpa16(so + OFF_BH, Bh + bo, 16u);
        cpa16(so + OFF_BL, Bl + bo, 16u);
    }
}

// ---------------- fp16 wmma GEMM core, mixed accumulators ----------------
// 8 warps: wm=wid&1 (64 rows), wn=wid>>1 (32 cols).
// accm (f32) += Ah*Bh ; accx (f16, full-rate) += Ah*Bl' + Al'*Bh  (lo scaled x2048)
template <bool GATHER>
__device__ __forceinline__ void gemm_tile(
    char* smem, u32 sb, int tid,
    const __half* __restrict__ Ah, const __half* __restrict__ Al,
    size_t a_stride, const int* rowTok, int rows,
    const __half* __restrict__ Bh, const __half* __restrict__ Bl,
    size_t b_stride, int kdim,
    wmma::fragment<wmma::accumulator, 16, 16, 16, float>  (&accm)[4][2],
    wmma::fragment<wmma::accumulator, 16, 16, 16, __half> (&accx)[4][2])
{
    int wid = tid >> 5;
    int warp_m = wid & 1, warp_n = wid >> 1;

#pragma unroll
    for (int i = 0; i < 4; i++)
#pragma unroll
        for (int j = 0; j < 2; j++) {
            wmma::fill_fragment(accm[i][j], 0.f);
            wmma::fill_fragment(accx[i][j], __float2half(0.f));
        }

    u32 stg_a[2] = { sb + SM_STG0, sb + SM_STG0 + STG_SZ };
    issue_chunk<GATHER>(stg_a[0], tid, 0, Ah, Al, a_stride, rowTok, rows, Bh, Bl, b_stride);
    cpa_commit();

    int nch = kdim / BK;
    for (int ch = 0; ch < nch; ch++) {
        if (ch + 1 < nch) {
            issue_chunk<GATHER>(stg_a[(ch + 1) & 1], tid, (ch + 1) * BK,
                                Ah, Al, a_stride, rowTok, rows, Bh, Bl, b_stride);
            cpa_commit();
            cpa_wait<1>();
        } else {
            cpa_wait<0>();
        }
        __syncthreads();

        char* stg = smem + SM_STG0 + (ch & 1) * STG_SZ;
        const __half* As_h = (const __half*)(stg + OFF_AH);
        const __half* As_l = (const __half*)(stg + OFF_AL);
        const __half* Bs_h = (const __half*)(stg + OFF_BH);
        const __half* Bs_l = (const __half*)(stg + OFF_BL);

#pragma unroll
        for (int ks = 0; ks < 2; ks++) {
            wmma::fragment<wmma::matrix_b, 16, 16, 16, __half, wmma::col_major> bh[2], bl[2];
#pragma unroll
            for (int j = 0; j < 2; j++) {
                int n = warp_n * 32 + j * 16;
                wmma::load_matrix_sync(bh[j], Bs_h + (size_t)n * PITCH + ks * 16, PITCH);
                wmma::load_matrix_sync(bl[j], Bs_l + (size_t)n * PITCH + ks * 16, PITCH);
            }
#pragma unroll
            for (int i = 0; i < 4; i++) {
                int m = warp_m * 64 + i * 16;
                wmma::fragment<wmma::matrix_a, 16, 16, 16, __half, wmma::row_major> ah, al;
                wmma::load_matrix_sync(ah, As_h + (size_t)m * PITCH + ks * 16, PITCH);
                wmma::load_matrix_sync(al, As_l + (size_t)m * PITCH + ks * 16, PITCH);
#pragma unroll
                for (int j = 0; j < 2; j++) {
                    wmma::mma_sync(accm[i][j], ah, bh[j], accm[i][j]);   // main, f32 acc
                    wmma::mma_sync(accx[i][j], ah, bl[j], accx[i][j]);   // cross, f16 acc
                    wmma::mma_sync(accx[i][j], al, bh[j], accx[i][j]);   // cross, f16 acc
                }
            }
        }
        __syncthreads();
    }
}

// ---------------- GEMM1: H1 = gelu(gather(X) @ Wfc[e]^T) ----------------
__global__ __launch_bounds__(256, 2) void k_gemm1(int) {
    int tile = blockIdx.x;
    if (tile >= g_numTiles) return;
    int e = g_tileE[tile], row0 = g_tileRow0[tile], rows = g_tileRows[tile];
    int col0 = blockIdx.y * BN;

    extern __shared__ char smem[];
    u32 sb = smem_u32(smem);
    int tid = threadIdx.x, wid = tid >> 5;
    int warp_m = wid & 1, warp_n = wid >> 1;

    int* rowTok = (int*)(smem + SM_ROWTOK);
    if (tid < BM) rowTok[tid] = (tid < rows) ? g_perm[row0 + tid] : -1;
    __syncthreads();

    wmma::fragment<wmma::accumulator, 16, 16, 16, float>  accm[4][2];
    wmma::fragment<wmma::accumulator, 16, 16, 16, __half> accx[4][2];
    const __half* Bh = g_Wfh + ((size_t)e * IDIM + col0) * HDIM;
    const __half* Bl = g_Wfl + ((size_t)e * IDIM + col0) * HDIM;
    gemm_tile<true>(smem, sb, tid, g_Xhi, g_Xlo, HDIM, rowTok, rows, Bh, Bl, HDIM, HDIM, accm, accx);

    float* st = (float*)smem;
    __syncthreads();
#pragma unroll
    for (int i = 0; i < 4; i++)
#pragma unroll
        for (int j = 0; j < 2; j++) {
            wmma::fragment<wmma::accumulator, 16, 16, 16, float> f;
#pragma unroll
            for (int k = 0; k < f.num_elements; k++)
                f.x[k] = accm[i][j].x[k] + __half2float(accx[i][j].x[k]) * INV_LOSCALE;
            wmma::store_matrix_sync(st + (size_t)(warp_m * 64 + i * 16) * SPITCH
                                       + warp_n * 32 + j * 16,
                                    f, SPITCH, wmma::mem_row_major);
        }
    __syncthreads();
    for (int u = tid; u < 128 * 16; u += 256) {   // 8 fp16 cols per unit
        int m = u >> 4, q = (u & 15) * 8;
        if (m < rows) {
            __half h8[8], l8[8];
#pragma unroll
            for (int c = 0; c < 8; c++) {
                float v = st[(size_t)m * SPITCH + q + c];
                float g = 0.5f * v * (1.f + erff(v * 0.70710678118654752f));
                __half h = __float2half(g);
                h8[c] = h;
                l8[c] = __float2half((g - __half2float(h)) * LOSCALE);
            }
            size_t o = (size_t)(row0 + m) * IDIM + col0 + q;
            *(uint4*)(g_H1h + o) = *(const uint4*)h8;
            *(uint4*)(g_H1l + o) = *(const uint4*)l8;
        }
    }
}

// ---------------- GEMM2: Y2 = H1 @ Wproj[e]^T ----------------
__global__ __launch_bounds__(256, 2) void k_gemm2(int) {
    int tile = blockIdx.x;
    if (tile >= g_numTiles) return;
    int e = g_tileE[tile], row0 = g_tileRow0[tile], rows = g_tileRows[tile];
    int col0 = blockIdx.y * BN;

    extern __shared__ char smem[];
    u32 sb = smem_u32(smem);
    int tid = threadIdx.x, wid = tid >> 5;
    int warp_m = wid & 1, warp_n = wid >> 1;

    wmma::fragment<wmma::accumulator, 16, 16, 16, float>  accm[4][2];
    wmma::fragment<wmma::accumulator, 16, 16, 16, __half> accx[4][2];
    const __half* Ah = g_H1h + (size_t)row0 * IDIM;
    const __half* Al = g_H1l + (size_t)row0 * IDIM;
    const __half* Bh = g_Wph + ((size_t)e * HDIM + col0) * IDIM;
    const __half* Bl = g_Wpl + ((size_t)e * HDIM + col0) * IDIM;
    gemm_tile<false>(smem, sb, tid, Ah, Al, IDIM, nullptr, rows, Bh, Bl, IDIM, IDIM, accm, accx);

    float* st = (float*)smem;
    __syncthreads();
#pragma unroll
    for (int i = 0; i < 4; i++)
#pragma unroll
        for (int j = 0; j < 2; j++) {
            wmma::fragment<wmma::accumulator, 16, 16, 16, float> f;
#pragma unroll
            for (int k = 0; k < f.num_elements; k++)
                f.x[k] = accm[i][j].x[k] + __half2float(accx[i][j].x[k]) * INV_LOSCALE;
            wmma::store_matrix_sync(st + (size_t)(warp_m * 64 + i * 16) * SPITCH
                                       + warp_n * 32 + j * 16,
                                    f, SPITCH, wmma::mem_row_major);
        }
    __syncthreads();
    for (int u = tid; u < 128 * 32; u += 256) {   // 4 floats per unit
        int m = u >> 5, q = (u & 31) * 4;
        if (m < rows) {
            size_t o = (size_t)(row0 + m) * HDIM + col0 + q;
            *(uint4*)(g_Y2 + o) = *(const uint4*)(st + (size_t)m * SPITCH + q);
        }
    }
}

// ---------------- combine ----------------
__global__ void k_combine(float* __restrict__ out) {
    int i4 = blockIdx.x * blockDim.x + threadIdx.x;
    if (i4 >= NTOK * (HDIM / 4)) return;
    int t = i4 / (HDIM / 4), h4 = i4 % (HDIM / 4);
    int p0 = g_slot[2*t], p1 = g_slot[2*t + 1];
    float w0 = g_wt[p0], w1 = g_wt[p1];
    float4 a = *(const float4*)(g_Y2 + (size_t)p0 * HDIM + h4 * 4);
    float4 b = *(const float4*)(g_Y2 + (size_t)p1 * HDIM + h4 * 4);
    float4 o;
    o.x = fmaf(w0, a.x, w1 * b.x);
    o.y = fmaf(w0, a.y, w1 * b.y);
    o.z = fmaf(w0, a.z, w1 * b.z);
    o.w = fmaf(w0, a.w, w1 * b.w);
    *((float4*)out + i4) = o;
}

// ---------------- launch ----------------
extern "C" void kernel_launch(void* const* d_in, const int* in_sizes, int n_in,
                              void* d_out, int out_size) {
    const float* X     = (const float*)d_in[0];
    const float* Wg    = (const float*)d_in[1];
    const float* Wfc   = (const float*)d_in[2];
    const float* Wproj = (const float*)d_in[3];
    float* out = (float*)d_out;

    int write_logits = (out_size >= NTOK * HDIM + NTOK * NEXP) ? 1 : 0;
    float* logits = out + (size_t)NTOK * HDIM;

    static int attr_done = 0;
    if (!attr_done) {
        cudaFuncSetAttribute(k_gemm1, cudaFuncAttributeMaxDynamicSharedMemorySize, DSMEM);
        cudaFuncSetAttribute(k_gemm2, cudaFuncAttributeMaxDynamicSharedMemorySize, DSMEM);
        attr_done = 1;
    }

    __half *xh, *xl, *wfh, *wfl, *wph, *wpl;
    cudaGetSymbolAddress((void**)&xh,  g_Xhi);  cudaGetSymbolAddress((void**)&xl,  g_Xlo);
    cudaGetSymbolAddress((void**)&wfh, g_Wfh);  cudaGetSymbolAddress((void**)&wfl, g_Wfl);
    cudaGetSymbolAddress((void**)&wph, g_Wph);  cudaGetSymbolAddress((void**)&wpl, g_Wpl);

    k_init<<<1, 32>>>();
    {
        int n4 = NTOK * HDIM / 4;
        k_split<<<(n4 + 255) / 256, 256>>>(X, xh, xl, n4);
    }
    {
        int n4 = NEXP * IDIM * HDIM / 4;
        k_split<<<(n4 + 255) / 256, 256>>>(Wfc, wfh, wfl, n4);
        k_split<<<(n4 + 255) / 256, 256>>>(Wproj, wph, wpl, n4);
    }
    k_router<<<NTOK / 8, 256>>>(X, Wg, logits, write_logits);
    k_scan<<<1, 1>>>();
    k_scatter<<<NTOK / 256, 256>>>();
    k_gemm1<<<dim3(MAXT, IDIM / BN), 256, DSMEM>>>(0);
    k_gemm2<<<dim3(MAXT, HDIM / BN), 256, DSMEM>>>(0);
    k_combine<<<(NTOK * (HDIM / 4) + 255) / 256, 256>>>(out);
}

// round 14
// speedup vs baseline: 5.9822x; 1.3202x over previous
#include <cuda_runtime.h>
#include <cuda_fp16.h>
#include <mma.h>
#include <math.h>

using namespace nvcuda;

// ---------------- problem constants ----------------
#define NTOK 8192
#define HDIM 1024
#define IDIM 2048
#define NEXP 8
#define NSLOT (NTOK*2)

#define BM 128
#define BN 128
#define BK 32
#define MAXT 136

#define PITCH 40          // fp16 elems; 80B row stride -> conflict-free ldmatrix
#define SPITCH 132        // float stage pitch (epilogue)
#define LOSCALE 2048.0f
#define INV_LOSCALE 4.8828125e-4f

// double-buffered smem layout (bytes): 3 tiles per stage (Ah, Al, Bh)
#define SM_ROWTOK 0
#define SM_STG0   1024
#define TILE_B    (128*PITCH*2)        // 10240 per operand tile
#define STG_SZ    (3*TILE_B)           // 30720 per stage
#define OFF_AH 0
#define OFF_AL (1*TILE_B)
#define OFF_BH (2*TILE_B)
#define MAINLOOP_B (SM_STG0 + 2*STG_SZ)    // 62464
#define EPI_B (128*SPITCH*4)               // 67584
#define DSMEM (EPI_B > MAINLOOP_B ? EPI_B : MAINLOOP_B)

typedef unsigned int u32;

// ---------------- device scratch ----------------
__device__ __half g_Xhi[(size_t)NTOK * HDIM];
__device__ __half g_Xlo[(size_t)NTOK * HDIM];     // scaled x2048
__device__ __half g_Wfh[(size_t)NEXP * IDIM * HDIM];   // weights: plain fp16
__device__ __half g_Wph[(size_t)NEXP * HDIM * IDIM];
__device__ __half g_H1h[(size_t)NSLOT * IDIM];
__device__ __half g_H1l[(size_t)NSLOT * IDIM];    // scaled x2048
__device__ float g_Y2[(size_t)NSLOT * HDIM];
__device__ int   g_perm[NSLOT];
__device__ float g_wt[NSLOT];
__device__ int   g_slot[NSLOT];
__device__ int   g_te[NSLOT];
__device__ float g_twt[NSLOT];
__device__ int   g_counts[NEXP];
__device__ int   g_offsets[NEXP];
__device__ int   g_cursors[NEXP];
__device__ int   g_numTiles;
__device__ int   g_tileE[MAXT];
__device__ int   g_tileRow0[MAXT];
__device__ int   g_tileRows[MAXT];

// ---------------- cp.async helpers ----------------
__device__ __forceinline__ u32 smem_u32(const void* p) {
    u32 a;
    asm("{ .reg .u64 t; cvta.to.shared.u64 t, %1; cvt.u32.u64 %0, t; }" : "=r"(a) : "l"(p));
    return a;
}
__device__ __forceinline__ void cpa16(u32 dst, const void* src, u32 srcsz) {
    asm volatile("cp.async.cg.shared.global [%0], [%1], 16, %2;"
                 :: "r"(dst), "l"(src), "r"(srcsz) : "memory");
}
__device__ __forceinline__ void cpa_commit() {
    asm volatile("cp.async.commit_group;" ::: "memory");
}
template <int N>
__device__ __forceinline__ void cpa_wait() {
    asm volatile("cp.async.wait_group %0;" :: "n"(N) : "memory");
}

// ---------------- small kernels ----------------
__global__ void k_init() {
    int i = threadIdx.x;
    if (i < NEXP) { g_counts[i] = 0; g_cursors[i] = 0; }
}

// fp16 two-level split: x = h + (l/2048)
__global__ void k_split(const float* __restrict__ s, __half* __restrict__ hi,
                        __half* __restrict__ lo, int n4) {
    int i = blockIdx.x * blockDim.x + threadIdx.x;
    if (i >= n4) return;
    float4 v = ((const float4*)s)[i];
    __half h0 = __float2half(v.x), h1 = __float2half(v.y);
    __half h2 = __float2half(v.z), h3 = __float2half(v.w);
    __half l0 = __float2half((v.x - __half2float(h0)) * LOSCALE);
    __half l1 = __float2half((v.y - __half2float(h1)) * LOSCALE);
    __half l2 = __float2half((v.z - __half2float(h2)) * LOSCALE);
    __half l3 = __float2half((v.w - __half2float(h3)) * LOSCALE);
    uint2 ph, pl;
    ph.x = (u32)__half_as_ushort(h0) | ((u32)__half_as_ushort(h1) << 16);
    ph.y = (u32)__half_as_ushort(h2) | ((u32)__half_as_ushort(h3) << 16);
    pl.x = (u32)__half_as_ushort(l0) | ((u32)__half_as_ushort(l1) << 16);
    pl.y = (u32)__half_as_ushort(l2) | ((u32)__half_as_ushort(l3) << 16);
    ((uint2*)hi)[i] = ph;
    ((uint2*)lo)[i] = pl;
}

// plain fp16 cast (weights)
__global__ void k_casth(const float* __restrict__ s, __half* __restrict__ hi, int n4) {
    int i = blockIdx.x * blockDim.x + threadIdx.x;
    if (i >= n4) return;
    float4 v = ((const float4*)s)[i];
    __half h0 = __float2half(v.x), h1 = __float2half(v.y);
    __half h2 = __float2half(v.z), h3 = __float2half(v.w);
    uint2 ph;
    ph.x = (u32)__half_as_ushort(h0) | ((u32)__half_as_ushort(h1) << 16);
    ph.y = (u32)__half_as_ushort(h2) | ((u32)__half_as_ushort(h3) << 16);
    ((uint2*)hi)[i] = ph;
}

__global__ void k_router(const float* __restrict__ X, const float* __restrict__ Wg,
                         float* __restrict__ logits, int write_logits) {
    int warp = threadIdx.x >> 5, lane = threadIdx.x & 31;
    int t = blockIdx.x * (blockDim.x >> 5) + warp;
    if (t >= NTOK) return;
    const float* xp = X + (size_t)t * HDIM;
    float acc[NEXP];
#pragma unroll
    for (int e = 0; e < NEXP; e++) acc[e] = 0.f;
    for (int k = lane; k < HDIM; k += 32) {
        float xv = __ldg(xp + k);
#pragma unroll
        for (int e = 0; e < NEXP; e++) acc[e] = fmaf(xv, __ldg(Wg + e * HDIM + k), acc[e]);
    }
#pragma unroll
    for (int e = 0; e < NEXP; e++) {
        acc[e] += __shfl_xor_sync(0xffffffffu, acc[e], 16);
        acc[e] += __shfl_xor_sync(0xffffffffu, acc[e], 8);
        acc[e] += __shfl_xor_sync(0xffffffffu, acc[e], 4);
        acc[e] += __shfl_xor_sync(0xffffffffu, acc[e], 2);
        acc[e] += __shfl_xor_sync(0xffffffffu, acc[e], 1);
    }
    if (lane == 0) {
        if (write_logits) {
#pragma unroll
            for (int e = 0; e < NEXP; e++) logits[(size_t)t * NEXP + e] = acc[e];
        }
        int i0 = 0;
#pragma unroll
        for (int e = 1; e < NEXP; e++) if (acc[e] > acc[i0]) i0 = e;
        int i1 = (i0 == 0) ? 1 : 0;
#pragma unroll
        for (int e = 0; e < NEXP; e++) if (e != i1 && e != i0 && acc[e] > acc[i1]) i1 = e;
        float d  = expf(acc[i1] - acc[i0]);
        float w0 = 1.f / (1.f + d);
        g_te[2*t] = i0;   g_twt[2*t] = w0;
        g_te[2*t+1] = i1; g_twt[2*t+1] = 1.f - w0;
        atomicAdd(&g_counts[i0], 1);
        atomicAdd(&g_counts[i1], 1);
    }
}

__global__ void k_scan() {
    int off = 0, t = 0;
    for (int e = 0; e < NEXP; e++) {
        g_offsets[e] = off;
        int c = g_counts[e];
        for (int r = 0; r < c; r += BM) {
            g_tileE[t] = e; g_tileRow0[t] = off + r;
            g_tileRows[t] = (c - r < BM) ? (c - r) : BM;
            t++;
        }
        off += c;
    }
    g_numTiles = t;
}

__global__ void k_scatter() {
    int t = blockIdx.x * blockDim.x + threadIdx.x;
    if (t >= NTOK) return;
#pragma unroll
    for (int s = 0; s < 2; s++) {
        int e = g_te[2*t + s];
        int pos = g_offsets[e] + atomicAdd(&g_cursors[e], 1);
        g_perm[pos] = t;
        g_wt[pos] = g_twt[2*t + s];
        g_slot[2*t + s] = pos;
    }
}

// ---------------- async chunk issue: Ah, Al, Bh tiles, 128x32 fp16 each ----------------
template <bool GATHER>
__device__ __forceinline__ void issue_chunk(
    u32 stg, int tid, int k0,
    const __half* __restrict__ Ah, const __half* __restrict__ Al,
    size_t a_stride, const int* rowTok, int rows,
    const __half* __restrict__ Bh, size_t b_stride)
{
#pragma unroll
    for (int t4 = 0; t4 < 2; t4++) {
        int u = tid + t4 * 256;          // 0..511 -> 128 rows x 4 16B units
        int m = u >> 2, kb = (u & 3) * 8;
        u32 so = stg + (u32)(m * PITCH + kb) * 2;
        u32 sz; int row;
        if (GATHER) {
            int tok = rowTok[m];
            sz  = (tok >= 0) ? 16u : 0u;
            row = (tok >= 0) ? tok : 0;
        } else {
            sz  = (m < rows) ? 16u : 0u;
            row = (m < rows) ? m : 0;
        }
        size_t ao = (size_t)row * a_stride + k0 + kb;
        cpa16(so + OFF_AH, Ah + ao, sz);
        cpa16(so + OFF_AL, Al + ao, sz);
        size_t bo = (size_t)m * b_stride + k0 + kb;
        cpa16(so + OFF_BH, Bh + bo, 16u);
    }
}

// ---------------- fp16 wmma GEMM core: 2-term split (A corrected, B plain) -------
// 8 warps: wm=wid&1 (64 rows), wn=wid>>1 (32 cols).
// accm (f32) += Ah*Bh ; accx (f16) += Al'*Bh   (Al scaled x2048)
template <bool GATHER>
__device__ __forceinline__ void gemm_tile(
    char* smem, u32 sb, int tid,
    const __half* __restrict__ Ah, const __half* __restrict__ Al,
    size_t a_stride, const int* rowTok, int rows,
    const __half* __restrict__ Bh, size_t b_stride, int kdim,
    wmma::fragment<wmma::accumulator, 16, 16, 16, float>  (&accm)[4][2],
    wmma::fragment<wmma::accumulator, 16, 16, 16, __half> (&accx)[4][2])
{
    int wid = tid >> 5;
    int warp_m = wid & 1, warp_n = wid >> 1;

#pragma unroll
    for (int i = 0; i < 4; i++)
#pragma unroll
        for (int j = 0; j < 2; j++) {
            wmma::fill_fragment(accm[i][j], 0.f);
            wmma::fill_fragment(accx[i][j], __float2half(0.f));
        }

    u32 stg_a[2] = { sb + SM_STG0, sb + SM_STG0 + STG_SZ };
    issue_chunk<GATHER>(stg_a[0], tid, 0, Ah, Al, a_stride, rowTok, rows, Bh, b_stride);
    cpa_commit();

    int nch = kdim / BK;
    for (int ch = 0; ch < nch; ch++) {
        if (ch + 1 < nch) {
            issue_chunk<GATHER>(stg_a[(ch + 1) & 1], tid, (ch + 1) * BK,
                                Ah, Al, a_stride, rowTok, rows, Bh, b_stride);
            cpa_commit();
            cpa_wait<1>();
        } else {
            cpa_wait<0>();
        }
        __syncthreads();

        char* stg = smem + SM_STG0 + (ch & 1) * STG_SZ;
        const __half* As_h = (const __half*)(stg + OFF_AH);
        const __half* As_l = (const __half*)(stg + OFF_AL);
        const __half* Bs_h = (const __half*)(stg + OFF_BH);

#pragma unroll
        for (int ks = 0; ks < 2; ks++) {
            wmma::fragment<wmma::matrix_b, 16, 16, 16, __half, wmma::col_major> bh[2];
#pragma unroll
            for (int j = 0; j < 2; j++) {
                int n = warp_n * 32 + j * 16;
                wmma::load_matrix_sync(bh[j], Bs_h + (size_t)n * PITCH + ks * 16, PITCH);
            }
#pragma unroll
            for (int i = 0; i < 4; i++) {
                int m = warp_m * 64 + i * 16;
                wmma::fragment<wmma::matrix_a, 16, 16, 16, __half, wmma::row_major> ah, al;
                wmma::load_matrix_sync(ah, As_h + (size_t)m * PITCH + ks * 16, PITCH);
                wmma::load_matrix_sync(al, As_l + (size_t)m * PITCH + ks * 16, PITCH);
#pragma unroll
                for (int j = 0; j < 2; j++) {
                    wmma::mma_sync(accm[i][j], ah, bh[j], accm[i][j]);   // main, f32 acc
                    wmma::mma_sync(accx[i][j], al, bh[j], accx[i][j]);   // cross, f16 acc
                }
            }
        }
        __syncthreads();
    }
}

// ---------------- GEMM1: H1 = gelu(gather(X) @ Wfc[e]^T) ----------------
__global__ __launch_bounds__(256, 2) void k_gemm1(int) {
    int tile = blockIdx.x;
    if (tile >= g_numTiles) return;
    int e = g_tileE[tile], row0 = g_tileRow0[tile], rows = g_tileRows[tile];
    int col0 = blockIdx.y * BN;

    extern __shared__ char smem[];
    u32 sb = smem_u32(smem);
    int tid = threadIdx.x, wid = tid >> 5;
    int warp_m = wid & 1, warp_n = wid >> 1;

    int* rowTok = (int*)(smem + SM_ROWTOK);
    if (tid < BM) rowTok[tid] = (tid < rows) ? g_perm[row0 + tid] : -1;
    __syncthreads();

    wmma::fragment<wmma::accumulator, 16, 16, 16, float>  accm[4][2];
    wmma::fragment<wmma::accumulator, 16, 16, 16, __half> accx[4][2];
    const __half* Bh = g_Wfh + ((size_t)e * IDIM + col0) * HDIM;
    gemm_tile<true>(smem, sb, tid, g_Xhi, g_Xlo, HDIM, rowTok, rows, Bh, HDIM, HDIM, accm, accx);

    float* st = (float*)smem;
    __syncthreads();
#pragma unroll
    for (int i = 0; i < 4; i++)
#pragma unroll
        for (int j = 0; j < 2; j++) {
            wmma::fragment<wmma::accumulator, 16, 16, 16, float> f;
#pragma unroll
            for (int k = 0; k < f.num_elements; k++)
                f.x[k] = accm[i][j].x[k] + __half2float(accx[i][j].x[k]) * INV_LOSCALE;
            wmma::store_matrix_sync(st + (size_t)(warp_m * 64 + i * 16) * SPITCH
                                       + warp_n * 32 + j * 16,
                                    f, SPITCH, wmma::mem_row_major);
        }
    __syncthreads();
    for (int u = tid; u < 128 * 16; u += 256) {   // 8 fp16 cols per unit
        int m = u >> 4, q = (u & 15) * 8;
        if (m < rows) {
            __half h8[8], l8[8];
#pragma unroll
            for (int c = 0; c < 8; c++) {
                float v = st[(size_t)m * SPITCH + q + c];
                float g = 0.5f * v * (1.f + erff(v * 0.70710678118654752f));
                __half h = __float2half(g);
                h8[c] = h;
                l8[c] = __float2half((g - __half2float(h)) * LOSCALE);
            }
            size_t o = (size_t)(row0 + m) * IDIM + col0 + q;
            *(uint4*)(g_H1h + o) = *(const uint4*)h8;
            *(uint4*)(g_H1l + o) = *(const uint4*)l8;
        }
    }
}

// ---------------- GEMM2: Y2 = H1 @ Wproj[e]^T ----------------
__global__ __launch_bounds__(256, 2) void k_gemm2(int) {
    int tile = blockIdx.x;
    if (tile >= g_numTiles) return;
    int e = g_tileE[tile], row0 = g_tileRow0[tile], rows = g_tileRows[tile];
    int col0 = blockIdx.y * BN;

    extern __shared__ char smem[];
    u32 sb = smem_u32(smem);
    int tid = threadIdx.x, wid = tid >> 5;
    int warp_m = wid & 1, warp_n = wid >> 1;

    wmma::fragment<wmma::accumulator, 16, 16, 16, float>  accm[4][2];
    wmma::fragment<wmma::accumulator, 16, 16, 16, __half> accx[4][2];
    const __half* Ah = g_H1h + (size_t)row0 * IDIM;
    const __half* Al = g_H1l + (size_t)row0 * IDIM;
    const __half* Bh = g_Wph + ((size_t)e * HDIM + col0) * IDIM;
    gemm_tile<false>(smem, sb, tid, Ah, Al, IDIM, nullptr, rows, Bh, IDIM, IDIM, accm, accx);

    float* st = (float*)smem;
    __syncthreads();
#pragma unroll
    for (int i = 0; i < 4; i++)
#pragma unroll
        for (int j = 0; j < 2; j++) {
            wmma::fragment<wmma::accumulator, 16, 16, 16, float> f;
#pragma unroll
            for (int k = 0; k < f.num_elements; k++)
                f.x[k] = accm[i][j].x[k] + __half2float(accx[i][j].x[k]) * INV_LOSCALE;
            wmma::store_matrix_sync(st + (size_t)(warp_m * 64 + i * 16) * SPITCH
                                       + warp_n * 32 + j * 16,
                                    f, SPITCH, wmma::mem_row_major);
        }
    __syncthreads();
    for (int u = tid; u < 128 * 32; u += 256) {   // 4 floats per unit
        int m = u >> 5, q = (u & 31) * 4;
        if (m < rows) {
            size_t o = (size_t)(row0 + m) * HDIM + col0 + q;
            *(uint4*)(g_Y2 + o) = *(const uint4*)(st + (size_t)m * SPITCH + q);
        }
    }
}

// ---------------- combine ----------------
__global__ void k_combine(float* __restrict__ out) {
    int i4 = blockIdx.x * blockDim.x + threadIdx.x;
    if (i4 >= NTOK * (HDIM / 4)) return;
    int t = i4 / (HDIM / 4), h4 = i4 % (HDIM / 4);
    int p0 = g_slot[2*t], p1 = g_slot[2*t + 1];
    float w0 = g_wt[p0], w1 = g_wt[p1];
    float4 a = *(const float4*)(g_Y2 + (size_t)p0 * HDIM + h4 * 4);
    float4 b = *(const float4*)(g_Y2 + (size_t)p1 * HDIM + h4 * 4);
    float4 o;
    o.x = fmaf(w0, a.x, w1 * b.x);
    o.y = fmaf(w0, a.y, w1 * b.y);
    o.z = fmaf(w0, a.z, w1 * b.z);
    o.w = fmaf(w0, a.w, w1 * b.w);
    *((float4*)out + i4) = o;
}

// ---------------- launch ----------------
extern "C" void kernel_launch(void* const* d_in, const int* in_sizes, int n_in,
                              void* d_out, int out_size) {
    const float* X     = (const float*)d_in[0];
    const float* Wg    = (const float*)d_in[1];
    const float* Wfc   = (const float*)d_in[2];
    const float* Wproj = (const float*)d_in[3];
    float* out = (float*)d_out;

    int write_logits = (out_size >= NTOK * HDIM + NTOK * NEXP) ? 1 : 0;
    float* logits = out + (size_t)NTOK * HDIM;

    static int attr_done = 0;
    if (!attr_done) {
        cudaFuncSetAttribute(k_gemm1, cudaFuncAttributeMaxDynamicSharedMemorySize, DSMEM);
        cudaFuncSetAttribute(k_gemm2, cudaFuncAttributeMaxDynamicSharedMemorySize, DSMEM);
        attr_done = 1;
    }

    __half *xh, *xl, *wfh, *wph;
    cudaGetSymbolAddress((void**)&xh,  g_Xhi);  cudaGetSymbolAddress((void**)&xl,  g_Xlo);
    cudaGetSymbolAddress((void**)&wfh, g_Wfh);  cudaGetSymbolAddress((void**)&wph, g_Wph);

    k_init<<<1, 32>>>();
    {
        int n4 = NTOK * HDIM / 4;
        k_split<<<(n4 + 255) / 256, 256>>>(X, xh, xl, n4);
    }
    {
        int n4 = NEXP * IDIM * HDIM / 4;
        k_casth<<<(n4 + 255) / 256, 256>>>(Wfc, wfh, n4);
        k_casth<<<(n4 + 255) / 256, 256>>>(Wproj, wph, n4);
    }
    k_router<<<NTOK / 8, 256>>>(X, Wg, logits, write_logits);
    k_scan<<<1, 1>>>();
    k_scatter<<<NTOK / 256, 256>>>();
    k_gemm1<<<dim3(MAXT, IDIM / BN), 256, DSMEM>>>(0);
    k_gemm2<<<dim3(MAXT, HDIM / BN), 256, DSMEM>>>(0);
    k_combine<<<(NTOK * (HDIM / 4) + 255) / 256, 256>>>(out);
}

// round 17
// speedup vs baseline: 10.4035x; 1.7391x over previous
#include <cuda_runtime.h>
#include <cuda_fp16.h>
#include <mma.h>
#include <math.h>

using namespace nvcuda;

// ---------------- problem constants ----------------
#define NTOK 8192
#define HDIM 1024
#define IDIM 2048
#define NEXP 8
#define NSLOT (NTOK*2)

#define BM 128
#define BN 128
#define BK 32
#define MAXT 136

#define PITCH 40          // fp16 elems; 80B row stride -> conflict-free ldmatrix
#define SPITCH 132        // float stage pitch (epilogue)

// 3-stage smem layout (bytes): 2 tiles per stage (Ah, Bh)
#define SM_ROWTOK 0
#define SM_STG0   1024
#define TILE_B    (128*PITCH*2)        // 10240 per operand tile
#define STG_SZ    (2*TILE_B)           // 20480 per stage
#define OFF_AH 0
#define OFF_BH TILE_B
#define NSTAGE 3
#define MAINLOOP_B (SM_STG0 + NSTAGE*STG_SZ)   // 62464
#define EPI_B (128*SPITCH*4)                   // 67584
#define DSMEM (EPI_B > MAINLOOP_B ? EPI_B : MAINLOOP_B)

typedef unsigned int u32;

// ---------------- device scratch ----------------
__device__ __half g_Xh[(size_t)NTOK * HDIM];
__device__ __half g_Wfh[(size_t)NEXP * IDIM * HDIM];
__device__ __half g_Wph[(size_t)NEXP * HDIM * IDIM];
__device__ __half g_H1h[(size_t)NSLOT * IDIM];
__device__ float g_Y2[(size_t)NSLOT * HDIM];
__device__ int   g_perm[NSLOT];
__device__ float g_wt[NSLOT];
__device__ int   g_slot[NSLOT];
__device__ int   g_te[NSLOT];
__device__ float g_twt[NSLOT];
__device__ int   g_counts[NEXP];
__device__ int   g_offsets[NEXP];
__device__ int   g_cursors[NEXP];
__device__ int   g_numTiles;
__device__ int   g_tileE[MAXT];
__device__ int   g_tileRow0[MAXT];
__device__ int   g_tileRows[MAXT];

// ---------------- cp.async helpers ----------------
__device__ __forceinline__ u32 smem_u32(const void* p) {
    u32 a;
    asm("{ .reg .u64 t; cvta.to.shared.u64 t, %1; cvt.u32.u64 %0, t; }" : "=r"(a) : "l"(p));
    return a;
}
__device__ __forceinline__ void cpa16(u32 dst, const void* src, u32 srcsz) {
    asm volatile("cp.async.cg.shared.global [%0], [%1], 16, %2;"
                 :: "r"(dst), "l"(src), "r"(srcsz) : "memory");
}
__device__ __forceinline__ void cpa_commit() {
    asm volatile("cp.async.commit_group;" ::: "memory");
}
template <int N>
__device__ __forceinline__ void cpa_wait() {
    asm volatile("cp.async.wait_group %0;" :: "n"(N) : "memory");
}

// ---------------- small kernels ----------------
__global__ void k_init() {
    int i = threadIdx.x;
    if (i < NEXP) { g_counts[i] = 0; g_cursors[i] = 0; }
}

// plain fp16 cast
__global__ void k_casth(const float* __restrict__ s, __half* __restrict__ hi, int n4) {
    int i = blockIdx.x * blockDim.x + threadIdx.x;
    if (i >= n4) return;
    float4 v = ((const float4*)s)[i];
    __half h0 = __float2half(v.x), h1 = __float2half(v.y);
    __half h2 = __float2half(v.z), h3 = __float2half(v.w);
    uint2 ph;
    ph.x = (u32)__half_as_ushort(h0) | ((u32)__half_as_ushort(h1) << 16);
    ph.y = (u32)__half_as_ushort(h2) | ((u32)__half_as_ushort(h3) << 16);
    ((uint2*)hi)[i] = ph;
}

__global__ void k_router(const float* __restrict__ X, const float* __restrict__ Wg,
                         float* __restrict__ logits, int write_logits) {
    int warp = threadIdx.x >> 5, lane = threadIdx.x & 31;
    int t = blockIdx.x * (blockDim.x >> 5) + warp;
    if (t >= NTOK) return;
    const float* xp = X + (size_t)t * HDIM;
    float acc[NEXP];
#pragma unroll
    for (int e = 0; e < NEXP; e++) acc[e] = 0.f;
    for (int k = lane; k < HDIM; k += 32) {
        float xv = __ldg(xp + k);
#pragma unroll
        for (int e = 0; e < NEXP; e++) acc[e] = fmaf(xv, __ldg(Wg + e * HDIM + k), acc[e]);
    }
#pragma unroll
    for (int e = 0; e < NEXP; e++) {
        acc[e] += __shfl_xor_sync(0xffffffffu, acc[e], 16);
        acc[e] += __shfl_xor_sync(0xffffffffu, acc[e], 8);
        acc[e] += __shfl_xor_sync(0xffffffffu, acc[e], 4);
        acc[e] += __shfl_xor_sync(0xffffffffu, acc[e], 2);
        acc[e] += __shfl_xor_sync(0xffffffffu, acc[e], 1);
    }
    if (lane == 0) {
        if (write_logits) {
#pragma unroll
            for (int e = 0; e < NEXP; e++) logits[(size_t)t * NEXP + e] = acc[e];
        }
        int i0 = 0;
#pragma unroll
        for (int e = 1; e < NEXP; e++) if (acc[e] > acc[i0]) i0 = e;
        int i1 = (i0 == 0) ? 1 : 0;
#pragma unroll
        for (int e = 0; e < NEXP; e++) if (e != i1 && e != i0 && acc[e] > acc[i1]) i1 = e;
        float d  = expf(acc[i1] - acc[i0]);
        float w0 = 1.f / (1.f + d);
        g_te[2*t] = i0;   g_twt[2*t] = w0;
        g_te[2*t+1] = i1; g_twt[2*t+1] = 1.f - w0;
        atomicAdd(&g_counts[i0], 1);
        atomicAdd(&g_counts[i1], 1);
    }
}

__global__ void k_scan() {
    int off = 0, t = 0;
    for (int e = 0; e < NEXP; e++) {
        g_offsets[e] = off;
        int c = g_counts[e];
        for (int r = 0; r < c; r += BM) {
            g_tileE[t] = e; g_tileRow0[t] = off + r;
            g_tileRows[t] = (c - r < BM) ? (c - r) : BM;
            t++;
        }
        off += c;
    }
    g_numTiles = t;
}

__global__ void k_scatter() {
    int t = blockIdx.x * blockDim.x + threadIdx.x;
    if (t >= NTOK) return;
#pragma unroll
    for (int s = 0; s < 2; s++) {
        int e = g_te[2*t + s];
        int pos = g_offsets[e] + atomicAdd(&g_cursors[e], 1);
        g_perm[pos] = t;
        g_wt[pos] = g_twt[2*t + s];
        g_slot[2*t + s] = pos;
    }
}

// ---------------- async chunk issue: Ah, Bh tiles, 128x32 fp16 each ----------------
template <bool GATHER>
__device__ __forceinline__ void issue_chunk(
    u32 stg, int tid, int k0,
    const __half* __restrict__ Ah, size_t a_stride, const int* rowTok, int rows,
    const __half* __restrict__ Bh, size_t b_stride)
{
#pragma unroll
    for (int t4 = 0; t4 < 2; t4++) {
        int u = tid + t4 * 256;          // 0..511 -> 128 rows x 4 16B units
        int m = u >> 2, kb = (u & 3) * 8;
        u32 so = stg + (u32)(m * PITCH + kb) * 2;
        u32 sz; int row;
        if (GATHER) {
            int tok = rowTok[m];
            sz  = (tok >= 0) ? 16u : 0u;
            row = (tok >= 0) ? tok : 0;
        } else {
            sz  = (m < rows) ? 16u : 0u;
            row = (m < rows) ? m : 0;
        }
        size_t ao = (size_t)row * a_stride + k0 + kb;
        cpa16(so + OFF_AH, Ah + ao, sz);
        size_t bo = (size_t)m * b_stride + k0 + kb;
        cpa16(so + OFF_BH, Bh + bo, 16u);
    }
}

// ---------------- plain fp16 wmma GEMM core, f32 acc, 3-stage pipeline -------
// 8 warps: wm=wid&1 (64 rows), wn=wid>>1 (32 cols). 1 MMA per frag pair.
template <bool GATHER>
__device__ __forceinline__ void gemm_tile(
    char* smem, u32 sb, int tid,
    const __half* __restrict__ Ah, size_t a_stride, const int* rowTok, int rows,
    const __half* __restrict__ Bh, size_t b_stride, int kdim,
    wmma::fragment<wmma::accumulator, 16, 16, 16, float> (&accm)[4][2])
{
    int wid = tid >> 5;
    int warp_m = wid & 1, warp_n = wid >> 1;

#pragma unroll
    for (int i = 0; i < 4; i++)
#pragma unroll
        for (int j = 0; j < 2; j++) wmma::fill_fragment(accm[i][j], 0.f);

    int nch = kdim / BK;
    issue_chunk<GATHER>(sb + SM_STG0, tid, 0, Ah, a_stride, rowTok, rows, Bh, b_stride);
    cpa_commit();
    issue_chunk<GATHER>(sb + SM_STG0 + STG_SZ, tid, BK, Ah, a_stride, rowTok, rows, Bh, b_stride);
    cpa_commit();

    for (int ch = 0; ch < nch; ch++) {
        if (ch + 2 < nch) {
            issue_chunk<GATHER>(sb + SM_STG0 + ((ch + 2) % NSTAGE) * STG_SZ, tid, (ch + 2) * BK,
                                Ah, a_stride, rowTok, rows, Bh, b_stride);
            cpa_commit();
            cpa_wait<2>();
        } else if (ch + 1 < nch) {
            cpa_wait<1>();
        } else {
            cpa_wait<0>();
        }
        __syncthreads();

        char* stg = smem + SM_STG0 + (ch % NSTAGE) * STG_SZ;
        const __half* As_h = (const __half*)(stg + OFF_AH);
        const __half* Bs_h = (const __half*)(stg + OFF_BH);

#pragma unroll
        for (int ks = 0; ks < 2; ks++) {
            wmma::fragment<wmma::matrix_b, 16, 16, 16, __half, wmma::col_major> bh[2];
#pragma unroll
            for (int j = 0; j < 2; j++) {
                int n = warp_n * 32 + j * 16;
                wmma::load_matrix_sync(bh[j], Bs_h + (size_t)n * PITCH + ks * 16, PITCH);
            }
#pragma unroll
            for (int i = 0; i < 4; i++) {
                int m = warp_m * 64 + i * 16;
                wmma::fragment<wmma::matrix_a, 16, 16, 16, __half, wmma::row_major> ah;
                wmma::load_matrix_sync(ah, As_h + (size_t)m * PITCH + ks * 16, PITCH);
#pragma unroll
                for (int j = 0; j < 2; j++)
                    wmma::mma_sync(accm[i][j], ah, bh[j], accm[i][j]);
            }
        }
        __syncthreads();
    }
}

// ---------------- GEMM1: H1 = gelu(gather(X) @ Wfc[e]^T) ----------------
__global__ __launch_bounds__(256, 2) void k_gemm1(int) {
    int tile = blockIdx.x;
    if (tile >= g_numTiles) return;
    int e = g_tileE[tile], row0 = g_tileRow0[tile], rows = g_tileRows[tile];
    int col0 = blockIdx.y * BN;

    extern __shared__ char smem[];
    u32 sb = smem_u32(smem);
    int tid = threadIdx.x, wid = tid >> 5;
    int warp_m = wid & 1, warp_n = wid >> 1;

    int* rowTok = (int*)(smem + SM_ROWTOK);
    if (tid < BM) rowTok[tid] = (tid < rows) ? g_perm[row0 + tid] : -1;
    __syncthreads();

    wmma::fragment<wmma::accumulator, 16, 16, 16, float> accm[4][2];
    const __half* Bh = g_Wfh + ((size_t)e * IDIM + col0) * HDIM;
    gemm_tile<true>(smem, sb, tid, g_Xh, HDIM, rowTok, rows, Bh, HDIM, HDIM, accm);

    float* st = (float*)smem;
    __syncthreads();
#pragma unroll
    for (int i = 0; i < 4; i++)
#pragma unroll
        for (int j = 0; j < 2; j++)
            wmma::store_matrix_sync(st + (size_t)(warp_m * 64 + i * 16) * SPITCH
                                       + warp_n * 32 + j * 16,
                                    accm[i][j], SPITCH, wmma::mem_row_major);
    __syncthreads();
    for (int u = tid; u < 128 * 16; u += 256) {   // 8 fp16 cols per unit
        int m = u >> 4, q = (u & 15) * 8;
        if (m < rows) {
            __half h8[8];
#pragma unroll
            for (int c = 0; c < 8; c++) {
                float v = st[(size_t)m * SPITCH + q + c];
                float g = 0.5f * v * (1.f + erff(v * 0.70710678118654752f));
                h8[c] = __float2half(g);
            }
            size_t o = (size_t)(row0 + m) * IDIM + col0 + q;
            *(uint4*)(g_H1h + o) = *(const uint4*)h8;
        }
    }
}

// ---------------- GEMM2: Y2 = H1 @ Wproj[e]^T ----------------
__global__ __launch_bounds__(256, 2) void k_gemm2(int) {
    int tile = blockIdx.x;
    if (tile >= g_numTiles) return;
    int e = g_tileE[tile], row0 = g_tileRow0[tile], rows = g_tileRows[tile];
    int col0 = blockIdx.y * BN;

    extern __shared__ char smem[];
    u32 sb = smem_u32(smem);
    int tid = threadIdx.x, wid = tid >> 5;
    int warp_m = wid & 1, warp_n = wid >> 1;

    wmma::fragment<wmma::accumulator, 16, 16, 16, float> accm[4][2];
    const __half* Ah = g_H1h + (size_t)row0 * IDIM;
    const __half* Bh = g_Wph + ((size_t)e * HDIM + col0) * IDIM;
    gemm_tile<false>(smem, sb, tid, Ah, IDIM, nullptr, rows, Bh, IDIM, IDIM, accm);

    float* st = (float*)smem;
    __syncthreads();
#pragma unroll
    for (int i = 0; i < 4; i++)
#pragma unroll
        for (int j = 0; j < 2; j++)
            wmma::store_matrix_sync(st + (size_t)(warp_m * 64 + i * 16) * SPITCH
                                       + warp_n * 32 + j * 16,
                                    accm[i][j], SPITCH, wmma::mem_row_major);
    __syncthreads();
    for (int u = tid; u < 128 * 32; u += 256) {   // 4 floats per unit
        int m = u >> 5, q = (u & 31) * 4;
        if (m < rows) {
            size_t o = (size_t)(row0 + m) * HDIM + col0 + q;
            *(uint4*)(g_Y2 + o) = *(const uint4*)(st + (size_t)m * SPITCH + q);
        }
    }
}

// ---------------- combine ----------------
__global__ void k_combine(float* __restrict__ out) {
    int i4 = blockIdx.x * blockDim.x + threadIdx.x;
    if (i4 >= NTOK * (HDIM / 4)) return;
    int t = i4 / (HDIM / 4), h4 = i4 % (HDIM / 4);
    int p0 = g_slot[2*t], p1 = g_slot[2*t + 1];
    float w0 = g_wt[p0], w1 = g_wt[p1];
    float4 a = *(const float4*)(g_Y2 + (size_t)p0 * HDIM + h4 * 4);
    float4 b = *(const float4*)(g_Y2 + (size_t)p1 * HDIM + h4 * 4);
    float4 o;
    o.x = fmaf(w0, a.x, w1 * b.x);
    o.y = fmaf(w0, a.y, w1 * b.y);
    o.z = fmaf(w0, a.z, w1 * b.z);
    o.w = fmaf(w0, a.w, w1 * b.w);
    *((float4*)out + i4) = o;
}

// ---------------- launch ----------------
extern "C" void kernel_launch(void* const* d_in, const int* in_sizes, int n_in,
                              void* d_out, int out_size) {
    const float* X     = (const float*)d_in[0];
    const float* Wg    = (const float*)d_in[1];
    const float* Wfc   = (const float*)d_in[2];
    const float* Wproj = (const float*)d_in[3];
    float* out = (float*)d_out;

    int write_logits = (out_size >= NTOK * HDIM + NTOK * NEXP) ? 1 : 0;
    float* logits = out + (size_t)NTOK * HDIM;

    static int attr_done = 0;
    if (!attr_done) {
        cudaFuncSetAttribute(k_gemm1, cudaFuncAttributeMaxDynamicSharedMemorySize, DSMEM);
        cudaFuncSetAttribute(k_gemm2, cudaFuncAttributeMaxDynamicSharedMemorySize, DSMEM);
        attr_done = 1;
    }

    __half *xh, *wfh, *wph;
    cudaGetSymbolAddress((void**)&xh,  g_Xh);
    cudaGetSymbolAddress((void**)&wfh, g_Wfh);
    cudaGetSymbolAddress((void**)&wph, g_Wph);

    k_init<<<1, 32>>>();
    {
        int n4 = NTOK * HDIM / 4;
        k_casth<<<(n4 + 255) / 256, 256>>>(X, xh, n4);
    }
    {
        int n4 = NEXP * IDIM * HDIM / 4;
        k_casth<<<(n4 + 255) / 256, 256>>>(Wfc, wfh, n4);
        k_casth<<<(n4 + 255) / 256, 256>>>(Wproj, wph, n4);
    }
    k_router<<<NTOK / 8, 256>>>(X, Wg, logits, write_logits);
    k_scan<<<1, 1>>>();
    k_scatter<<<NTOK / 256, 256>>>();
    k_gemm1<<<dim3(MAXT, IDIM / BN), 256, DSMEM>>>(0);
    k_gemm2<<<dim3(MAXT, HDIM / BN), 256, DSMEM>>>(0);
    k_combine<<<(NTOK * (HDIM / 4) + 255) / 256, 256>>>(out);
}